// round 9
// baseline (speedup 1.0000x reference)
#include <cuda_runtime.h>
#include <cuda_fp16.h>
#include <math.h>
#include <stdint.h>

// ---------------- problem shape ----------------
#define Bc 4
#define Sc 2048
#define Dc 1024
#define Mc (Bc * Sc)
#define D3 (3 * Dc)

// ---------------- scratch (device globals; no allocation allowed) ----------
__device__ __align__(256) __half g_xn  [(size_t)Mc * Dc];
__device__ __align__(256) __half g_qkv [(size_t)Mc * D3];
__device__ __align__(256) __half g_vt  [(size_t)Bc * Dc * Sc];
__device__ __align__(256) float  g_s   [(size_t)Bc * Sc * Sc];
__device__ __align__(256) __half g_a   [(size_t)Bc * Sc * Sc];
__device__ __align__(256) __half g_ao  [(size_t)Mc * Dc];
__device__ __align__(256) float  g_h   [(size_t)Mc * Dc];
__device__ __align__(256) __half g_m   [(size_t)Mc * Dc];
__device__ __align__(256) __half g_f   [(size_t)Mc * Dc];
__device__ __align__(256) __half g_wt  [6][(size_t)Dc * Dc];
__device__ __align__(256) float  g_bqkv[D3];

// ---------------- PTX helpers ----------------
__device__ __forceinline__ uint32_t s2u(const void* p) {
    uint32_t a;
    asm("{ .reg .u64 t; cvta.to.shared.u64 t, %1; cvt.u32.u64 %0, t; }"
        : "=r"(a) : "l"(p));
    return a;
}
__device__ __forceinline__ void cp16(uint32_t s, const void* g) {
    asm volatile("cp.async.cg.shared.global [%0], [%1], 16;" :: "r"(s), "l"(g));
}
#define CP_COMMIT() asm volatile("cp.async.commit_group;" ::: "memory")
#define CP_WAIT2()  asm volatile("cp.async.wait_group 2;" ::: "memory")
#define CP_WAIT0()  asm volatile("cp.async.wait_group 0;" ::: "memory")

__device__ __forceinline__ void ldmat4(uint32_t (&r)[4], uint32_t addr) {
    asm volatile("ldmatrix.sync.aligned.m8n8.x4.shared.b16 {%0,%1,%2,%3}, [%4];"
                 : "=r"(r[0]), "=r"(r[1]), "=r"(r[2]), "=r"(r[3]) : "r"(addr));
}
__device__ __forceinline__ void mma16816(float (&d)[4], const uint32_t (&a)[4],
                                         const uint32_t b0, const uint32_t b1) {
    asm volatile(
        "mma.sync.aligned.m16n8k16.row.col.f32.f16.f16.f32 "
        "{%0,%1,%2,%3},{%4,%5,%6,%7},{%8,%9},{%0,%1,%2,%3};"
        : "+f"(d[0]), "+f"(d[1]), "+f"(d[2]), "+f"(d[3])
        : "r"(a[0]), "r"(a[1]), "r"(a[2]), "r"(a[3]), "r"(b0), "r"(b1));
}

// ---------------- fp16 mma GEMM (64x64 warp tile, 3-stage, BK=64) ----------
// C = alpha * A[.,K] (x) B[.,K]^T    (both operands row-major over K, strided)
#define E_SC  0
#define E_FBR 2
#define E_H   7
#define E_HB  8
#define E_HBR 9

#define BKA 64                         // K per stage (fp16)
#define SSTR 72                        // padded smem row stride in halves (144 B)
#define STG_B (128 * SSTR * 2)         // one operand tile = 18432 B
#define STAGE_B (2 * STG_B)            // A+B per stage   = 36864 B
#define NSTG 3
#define SMEM_SZ (NSTG * STAGE_B)       // 110592 B

template <int EPI, bool CSKIP, bool CKLIM>
__global__ __launch_bounds__(128, 2)
void tgemm(const __half* __restrict__ A2, const __half* __restrict__ B2,
           const float* __restrict__ bias, const float* __restrict__ res,
           void* __restrict__ Cp, int Ksrc, int Nsrc, float alpha,
           long aRows, long bRows, long cRows, int lda, int ldb)
{
    const int brow = blockIdx.y * 128;
    const int bcol = blockIdx.x * 128;
    if (CSKIP && bcol > brow + 127) return;
    const int z = blockIdx.z;

    extern __shared__ __align__(16) char smem[];
    const uint32_t sb = s2u(smem);

    const int tid = threadIdx.x;
    const int lane = tid & 31;
    const int w = tid >> 5;
    const int wm = (w & 1) * 64;
    const int wn = (w >> 1) * 64;

    const __half* Arow = A2 + ((long)z * aRows + brow) * (long)lda;
    const __half* Brow = B2 + ((long)z * bRows + bcol) * (long)ldb;

    const int nk = (CKLIM ? min(Ksrc, brow + 128) : Ksrc) / BKA;

    float acc[4][8][4];
#pragma unroll
    for (int i = 0; i < 4; ++i)
#pragma unroll
        for (int j = 0; j < 8; ++j)
#pragma unroll
            for (int u = 0; u < 4; ++u) acc[i][j][u] = 0.f;

    auto load_tile = [&](int t) {
        const int k0 = t * BKA;
        const uint32_t base = sb + (t % NSTG) * STAGE_B;
#pragma unroll
        for (int it = 0; it < 8; ++it) {
            const int idx = tid + it * 128;
            const int row = idx >> 3;
            const int ch  = idx & 7;
            const uint32_t off = row * (SSTR * 2) + ch * 16;
            cp16(base + off,         Arow + (long)row * lda + k0 + ch * 8);
            cp16(base + STG_B + off, Brow + (long)row * ldb + k0 + ch * 8);
        }
    };

    const int a_moff = lane & 15;
    const int a_koff = (lane >> 4) * 8;
    const int b_noff = (lane & 7) + (lane >> 4) * 8;
    const int b_koff = ((lane >> 3) & 1) * 8;

    load_tile(0); CP_COMMIT();
    load_tile(1); CP_COMMIT();

    for (int t = 0; t < nk; ++t) {
        if (t + 2 < nk) load_tile(t + 2);
        CP_COMMIT();
        // keep up to 2 groups in flight; stage t is guaranteed resident
        if (t + 2 < nk) CP_WAIT2(); else CP_WAIT0();
        __syncthreads();

        const uint32_t abase = sb + (t % NSTG) * STAGE_B;
        const uint32_t bbase = abase + STG_B;
#pragma unroll
        for (int ks = 0; ks < 4; ++ks) {
            uint32_t a[4][4];
#pragma unroll
            for (int mi = 0; mi < 4; ++mi)
                ldmat4(a[mi], abase + (uint32_t)((wm + mi * 16 + a_moff) * (SSTR * 2)
                                                 + (ks * 16 + a_koff) * 2));
            uint32_t b[8][2];
#pragma unroll
            for (int np = 0; np < 4; ++np) {
                uint32_t bb[4];
                ldmat4(bb, bbase + (uint32_t)((wn + np * 16 + b_noff) * (SSTR * 2)
                                              + (ks * 16 + b_koff) * 2));
                b[np * 2][0] = bb[0]; b[np * 2][1] = bb[1];
                b[np * 2 + 1][0] = bb[2]; b[np * 2 + 1][1] = bb[3];
            }
#pragma unroll
            for (int mi = 0; mi < 4; ++mi)
#pragma unroll
                for (int nj = 0; nj < 8; ++nj)
                    mma16816(acc[mi][nj], a[mi], b[nj][0], b[nj][1]);
        }
        __syncthreads();   // stage (t+3)%3 buffer free for next iter's loads
    }

    // ---------------- epilogue ----------------
#pragma unroll
    for (int mi = 0; mi < 4; ++mi) {
#pragma unroll
        for (int half_ = 0; half_ < 2; ++half_) {
            const int r = brow + wm + mi * 16 + (lane >> 2) + half_ * 8;
#pragma unroll
            for (int nj = 0; nj < 8; ++nj) {
                const int c = bcol + wn + nj * 8 + 2 * (lane & 3);
                float v0 = acc[mi][nj][half_ * 2 + 0] * alpha;
                float v1 = acc[mi][nj][half_ * 2 + 1] * alpha;

                if (EPI == E_SC || EPI == E_FBR) {
                    if (EPI == E_FBR) {
                        v0 += bias[c]; v1 += bias[c + 1];
                        const float2 rv = *reinterpret_cast<const float2*>(
                            res + (long)r * Nsrc + c);
                        v0 += rv.x; v1 += rv.y;
                    }
                    float2 o; o.x = v0; o.y = v1;
                    *reinterpret_cast<float2*>(
                        (float*)Cp + ((long)z * cRows + r) * (long)Nsrc + c) = o;
                } else {
                    if (EPI == E_HB || EPI == E_HBR) { v0 += bias[c]; v1 += bias[c + 1]; }
                    if (EPI == E_HBR) { v0 = fmaxf(v0, 0.f); v1 = fmaxf(v1, 0.f); }
                    __half2 o2 = __floats2half2_rn(v0, v1);
                    *reinterpret_cast<__half2*>(
                        (__half*)Cp + ((long)z * cRows + r) * (long)Nsrc + c) = o2;
                }
            }
        }
    }
}

// ---------------- LayerNorm -> fp16 output (vectorized) ----------------
__global__ __launch_bounds__(256)
void layernorm_h(const float* __restrict__ x, const float* __restrict__ gamma,
                 const float* __restrict__ beta, __half* __restrict__ y)
{
    const long rowi = blockIdx.x;
    const int tid = threadIdx.x;
    const int lane = tid & 31;
    const int wid = tid >> 5;
    __shared__ float ws[8];

    const float4 xv = reinterpret_cast<const float4*>(x + rowi * Dc)[tid];

    float s = xv.x + xv.y + xv.z + xv.w;
#pragma unroll
    for (int o = 16; o > 0; o >>= 1) s += __shfl_xor_sync(0xffffffffu, s, o);
    if (lane == 0) ws[wid] = s;
    __syncthreads();
    float tot = 0.f;
#pragma unroll
    for (int i = 0; i < 8; ++i) tot += ws[i];
    const float mean = tot * (1.f / (float)Dc);
    __syncthreads();

    const float d0 = xv.x - mean, d1 = xv.y - mean, d2 = xv.z - mean, d3 = xv.w - mean;
    float v = d0 * d0 + d1 * d1 + d2 * d2 + d3 * d3;
#pragma unroll
    for (int o = 16; o > 0; o >>= 1) v += __shfl_xor_sync(0xffffffffu, v, o);
    if (lane == 0) ws[wid] = v;
    __syncthreads();
    float vtot = 0.f;
#pragma unroll
    for (int i = 0; i < 8; ++i) vtot += ws[i];
    const float var = vtot * (1.f / (float)(Dc - 1));   // ddof=1
    const float inv = 1.f / (sqrtf(var) + 1e-6f);       // eps on std

    const float4 gv = reinterpret_cast<const float4*>(gamma)[tid];
    const float4 bv = reinterpret_cast<const float4*>(beta)[tid];
    const float r0 = gv.x * d0 * inv + bv.x;
    const float r1 = gv.y * d1 * inv + bv.y;
    const float r2 = gv.z * d2 * inv + bv.z;
    const float r3 = gv.w * d3 * inv + bv.w;

    __half2* yr = reinterpret_cast<__half2*>(y + rowi * Dc);
    yr[2 * tid]     = __floats2half2_rn(r0, r1);
    yr[2 * tid + 1] = __floats2half2_rn(r2, r3);
}

// ---------------- causal softmax, single gmem read (smem row cache) --------
__global__ __launch_bounds__(256)
void softmax_h(const float* __restrict__ sc, __half* __restrict__ a)
{
    const int m = blockIdx.x;
    const int b = blockIdx.y;
    const float* row = sc + ((long)b * Sc + m) * (long)Sc;
    __half* orow = a + ((long)b * Sc + m) * (long)Sc;
    const int n = m + 1;
    const int tid = threadIdx.x;
    const int lane = tid & 31;
    const int wid = tid >> 5;

    __shared__ float sr[Sc];
    __shared__ float red[8];

    float lmax = -1e30f;
    for (int i = tid; i < n; i += 256) {
        const float v = row[i];
        sr[i] = v;
        lmax = fmaxf(lmax, v);
    }
#pragma unroll
    for (int o = 16; o > 0; o >>= 1)
        lmax = fmaxf(lmax, __shfl_xor_sync(0xffffffffu, lmax, o));
    if (lane == 0) red[wid] = lmax;
    __syncthreads();
    float gmax = -1e30f;
#pragma unroll
    for (int i = 0; i < 8; ++i) gmax = fmaxf(gmax, red[i]);
    __syncthreads();

    float lsum = 0.f;
    for (int i = tid; i < n; i += 256) {
        const float e = __expf(sr[i] - gmax);
        sr[i] = e;
        lsum += e;
    }
#pragma unroll
    for (int o = 16; o > 0; o >>= 1) lsum += __shfl_xor_sync(0xffffffffu, lsum, o);
    if (lane == 0) red[wid] = lsum;
    __syncthreads();
    float tot = 0.f;
#pragma unroll
    for (int i = 0; i < 8; ++i) tot += red[i];
    const float inv = 1.f / tot;

    for (int i = tid; i < n; i += 256)
        orow[i] = __float2half_rn(sr[i] * inv);
    const int lim = (m | 127);
    for (int i = n + tid; i <= lim; i += 256) orow[i] = __float2half_rn(0.f);
}

// ---------------- batched transpose f32 -> fp16 (all 6 weights, 1 launch) --
__global__ __launch_bounds__(256)
void trans_f2h6(const float* __restrict__ s0, const float* __restrict__ s1,
                const float* __restrict__ s2, const float* __restrict__ s3,
                const float* __restrict__ s4, const float* __restrict__ s5,
                __half* __restrict__ dstBase)
{
    const int zi = blockIdx.z;
    const float* src = (zi == 0) ? s0 : (zi == 1) ? s1 : (zi == 2) ? s2
                    : (zi == 3) ? s3 : (zi == 4) ? s4 : s5;
    __half* dst = dstBase + (size_t)zi * Dc * Dc;

    __shared__ float t[32][33];
    const int c0 = blockIdx.x * 32;
    const int r0 = blockIdx.y * 32;
    const int tx = threadIdx.x, ty = threadIdx.y;  // 32 x 8

#pragma unroll
    for (int i = 0; i < 4; ++i)
        t[ty + 8 * i][tx] = src[(long)(r0 + ty + 8 * i) * Dc + c0 + tx];
    __syncthreads();

#pragma unroll
    for (int i = 0; i < 4; ++i) {
        const int c = c0 + ty + 8 * i;
        const int r = r0 + tx;
        dst[(long)c * Dc + r] = __float2half_rn(t[tx][ty + 8 * i]);
    }
}

// ---------------- transpose fp16 -> fp16 (V slice of qkv), per batch -------
__global__ __launch_bounds__(256)
void trans_h2h(const __half* __restrict__ src, __half* __restrict__ dst,
               int R, int C, int srcStride, long srcBatch, long dstBatch)
{
    const int zb = blockIdx.z;
    src += (long)zb * srcBatch;
    dst += (long)zb * dstBatch;
    __shared__ __half t[32][34];
    const int c0 = blockIdx.x * 32;
    const int r0 = blockIdx.y * 32;
    const int tx = threadIdx.x, ty = threadIdx.y;

#pragma unroll
    for (int i = 0; i < 4; ++i)
        t[ty + 8 * i][tx] = src[(long)(r0 + ty + 8 * i) * srcStride + c0 + tx];
    __syncthreads();

#pragma unroll
    for (int i = 0; i < 4; ++i) {
        const int c = c0 + ty + 8 * i;
        const int r = r0 + tx;
        dst[(long)c * R + r] = t[tx][ty + 8 * i];
    }
}

// ---------------- bias concat ----------------
__global__ __launch_bounds__(256)
void concat_bias(const float* __restrict__ bq, const float* __restrict__ bk,
                 const float* __restrict__ bv, float* __restrict__ o)
{
    const int i = blockIdx.x * 256 + threadIdx.x;
    if (i < Dc) {
        o[i] = bq[i];
        o[Dc + i] = bk[i];
        o[2 * Dc + i] = bv[i];
    }
}

// ---------------------------------------------------------------------------
extern "C" void kernel_launch(void* const* d_in, const int* in_sizes, int n_in,
                              void* d_out, int out_size)
{
    const float* x   = (const float*)d_in[0];
    const float* wq  = (const float*)d_in[1];
    const float* bq  = (const float*)d_in[2];
    const float* wk  = (const float*)d_in[3];
    const float* bk  = (const float*)d_in[4];
    const float* wv  = (const float*)d_in[5];
    const float* bv  = (const float*)d_in[6];
    const float* wo  = (const float*)d_in[7];
    const float* bo  = (const float*)d_in[8];
    const float* w1  = (const float*)d_in[9];
    const float* b1  = (const float*)d_in[10];
    const float* w2  = (const float*)d_in[11];
    const float* b2  = (const float*)d_in[12];
    const float* g1  = (const float*)d_in[13];
    const float* be1 = (const float*)d_in[14];
    const float* g2  = (const float*)d_in[15];
    const float* be2 = (const float*)d_in[16];
    float* out = (float*)d_out;

    __half *xn, *qkv, *vt, *a, *ao, *m, *f, *wt;
    float *s, *h, *bqkv;
    cudaGetSymbolAddress((void**)&xn,  g_xn);
    cudaGetSymbolAddress((void**)&qkv, g_qkv);
    cudaGetSymbolAddress((void**)&vt,  g_vt);
    cudaGetSymbolAddress((void**)&s,   g_s);
    cudaGetSymbolAddress((void**)&a,   g_a);
    cudaGetSymbolAddress((void**)&ao,  g_ao);
    cudaGetSymbolAddress((void**)&h,   g_h);
    cudaGetSymbolAddress((void**)&m,   g_m);
    cudaGetSymbolAddress((void**)&f,   g_f);
    cudaGetSymbolAddress((void**)&wt,  g_wt);
    cudaGetSymbolAddress((void**)&bqkv, g_bqkv);

    __half* wot = wt + 3L * Dc * Dc;
    __half* w1t = wt + 4L * Dc * Dc;
    __half* w2t = wt + 5L * Dc * Dc;

    cudaFuncSetAttribute((const void*)tgemm<E_HB,  false, false>, cudaFuncAttributeMaxDynamicSharedMemorySize, SMEM_SZ);
    cudaFuncSetAttribute((const void*)tgemm<E_SC,  true,  false>, cudaFuncAttributeMaxDynamicSharedMemorySize, SMEM_SZ);
    cudaFuncSetAttribute((const void*)tgemm<E_H,   false, true >, cudaFuncAttributeMaxDynamicSharedMemorySize, SMEM_SZ);
    cudaFuncSetAttribute((const void*)tgemm<E_FBR, false, false>, cudaFuncAttributeMaxDynamicSharedMemorySize, SMEM_SZ);
    cudaFuncSetAttribute((const void*)tgemm<E_HBR, false, false>, cudaFuncAttributeMaxDynamicSharedMemorySize, SMEM_SZ);

    const float inv_sqrt_s = 1.0f / sqrtf((float)Sc);
    const dim3 tb(32, 8);
    const dim3 gW6(Dc / 32, Dc / 32, 6);
    const dim3 gV(Dc / 32, Sc / 32, Bc);
    const dim3 gQKV(D3 / 128, Mc / 128, 1);      // 24 x 64
    const dim3 gProj(Dc / 128, Mc / 128, 1);     // 8 x 64
    const dim3 gScore(Sc / 128, Sc / 128, Bc);   // 16 x 16 x 4
    const dim3 gAV(Dc / 128, Sc / 128, Bc);      // 8 x 16 x 4

    // all 6 weight transposes in one launch (QKV rows contiguous in g_wt)
    trans_f2h6<<<gW6, tb>>>(wq, wk, wv, wo, w1, w2, wt);
    concat_bias<<<4, 256>>>(bq, bk, bv, bqkv);

    // 1) LN1 -> xn (fp16)
    layernorm_h<<<Mc, 256>>>(x, g1, be1, xn);

    // 2) fused QKV projection: [M,1024] @ [3072,1024]^T -> [M,3072] fp16
    tgemm<E_HB, false, false><<<gQKV, 128, SMEM_SZ>>>(
        xn, wt, bqkv, nullptr, qkv, Dc, D3, 1.f, 0, 0, 0, Dc, Dc);

    // 3) v slice -> vt (transpose per batch)
    trans_h2h<<<gV, tb>>>(qkv + 2 * Dc, vt, Sc, Dc, D3,
                          (long)Sc * D3, (long)Dc * Sc);

    // 4) scores = (q k^T)/sqrt(S), causal tiles skipped (f32 out)
    tgemm<E_SC, true, false><<<gScore, 128, SMEM_SZ>>>(
        qkv, qkv + Dc, nullptr, nullptr, s, Dc, Sc, inv_sqrt_s,
        Sc, Sc, Sc, D3, D3);

    // 5) softmax -> a (fp16 + zero pad)
    softmax_h<<<dim3(Sc, Bc), 256>>>(s, a);

    // 6) attn @ V with block-K limit -> ao (fp16)
    tgemm<E_H, false, true><<<gAV, 128, SMEM_SZ>>>(
        a, vt, nullptr, nullptr, ao, Sc, Dc, 1.f, Sc, Dc, Sc, Sc, Sc);

    // 7) h = ao @ wo + bo + x (f32)
    tgemm<E_FBR, false, false><<<gProj, 128, SMEM_SZ>>>(
        ao, wot, bo, x, h, Dc, Dc, 1.f, 0, 0, 0, Dc, Dc);

    // 8) LN2 -> m (fp16)
    layernorm_h<<<Mc, 256>>>(h, g2, be2, m);

    // 9) f = relu(m @ w1 + b1) (fp16)
    tgemm<E_HBR, false, false><<<gProj, 128, SMEM_SZ>>>(
        m, w1t, b1, nullptr, f, Dc, Dc, 1.f, 0, 0, 0, Dc, Dc);

    // 10) out = f @ w2 + b2 + h (f32)
    tgemm<E_FBR, false, false><<<gProj, 128, SMEM_SZ>>>(
        f, w2t, b2, h, out, Dc, Dc, 1.f, 0, 0, 0, Dc, Dc);
}

// round 11
// speedup vs baseline: 1.5962x; 1.5962x over previous
#include <cuda_runtime.h>
#include <cuda_fp16.h>
#include <math.h>
#include <stdint.h>

// ---------------- problem shape ----------------
#define Bc 4
#define Sc 2048
#define Dc 1024
#define Mc (Bc * Sc)
#define D3 (3 * Dc)

// ---------------- scratch (device globals; no allocation allowed) ----------
__device__ __align__(256) __half g_xn  [(size_t)Mc * Dc];
__device__ __align__(256) __half g_qkv [(size_t)Mc * D3];
__device__ __align__(256) __half g_vt  [(size_t)Bc * Dc * Sc];
__device__ __align__(256) float  g_s   [(size_t)Bc * Sc * Sc];
__device__ __align__(256) __half g_a   [(size_t)Bc * Sc * Sc];
__device__ __align__(256) __half g_ao  [(size_t)Mc * Dc];
__device__ __align__(256) float  g_h   [(size_t)Mc * Dc];
__device__ __align__(256) __half g_m   [(size_t)Mc * Dc];
__device__ __align__(256) __half g_f   [(size_t)Mc * Dc];
__device__ __align__(256) __half g_wt  [6][(size_t)Dc * Dc];
__device__ __align__(256) float  g_bqkv[D3];

// ---------------- PTX helpers ----------------
__device__ __forceinline__ uint32_t s2u(const void* p) {
    uint32_t a;
    asm("{ .reg .u64 t; cvta.to.shared.u64 t, %1; cvt.u32.u64 %0, t; }"
        : "=r"(a) : "l"(p));
    return a;
}
__device__ __forceinline__ void cp16(uint32_t s, const void* g) {
    asm volatile("cp.async.cg.shared.global [%0], [%1], 16;" :: "r"(s), "l"(g));
}
#define CP_COMMIT() asm volatile("cp.async.commit_group;" ::: "memory")
#define CP_WAIT1()  asm volatile("cp.async.wait_group 1;" ::: "memory")

__device__ __forceinline__ void ldmat4(uint32_t (&r)[4], uint32_t addr) {
    asm volatile("ldmatrix.sync.aligned.m8n8.x4.shared.b16 {%0,%1,%2,%3}, [%4];"
                 : "=r"(r[0]), "=r"(r[1]), "=r"(r[2]), "=r"(r[3]) : "r"(addr));
}
__device__ __forceinline__ void mma16816(float (&d)[4], const uint32_t (&a)[4],
                                         const uint32_t b0, const uint32_t b1) {
    asm volatile(
        "mma.sync.aligned.m16n8k16.row.col.f32.f16.f16.f32 "
        "{%0,%1,%2,%3},{%4,%5,%6,%7},{%8,%9},{%0,%1,%2,%3};"
        : "+f"(d[0]), "+f"(d[1]), "+f"(d[2]), "+f"(d[3])
        : "r"(a[0]), "r"(a[1]), "r"(a[2]), "r"(a[3]), "r"(b0), "r"(b1));
}

// ---------------- fp16 mma GEMM (64x64 warp tile, 3-stage, BK=64) ----------
// C = alpha * A[.,K] (x) B[.,K]^T    (both operands row-major over K, strided)
#define E_SC  0
#define E_FBR 2
#define E_H   7
#define E_HB  8
#define E_HBR 9

#define BKA 64                         // K per stage (fp16)
#define SSTR 72                        // padded smem row stride in halves (144 B)
#define STG_B (128 * SSTR * 2)         // one operand tile = 18432 B
#define STAGE_B (2 * STG_B)            // A+B per stage   = 36864 B
#define NSTG 3
#define SMEM_SZ (NSTG * STAGE_B)       // 110592 B

template <int EPI, bool CSKIP, bool CKLIM>
__global__ __launch_bounds__(128, 2)
void tgemm(const __half* __restrict__ A2, const __half* __restrict__ B2,
           const float* __restrict__ bias, const float* __restrict__ res,
           void* __restrict__ Cp, int Ksrc, int Nsrc, float alpha,
           long aRows, long bRows, long cRows, int lda, int ldb)
{
    const int brow = blockIdx.y * 128;
    const int bcol = blockIdx.x * 128;
    if (CSKIP && bcol > brow + 127) return;
    const int z = blockIdx.z;

    extern __shared__ __align__(16) char smem[];
    const uint32_t sb = s2u(smem);

    const int tid = threadIdx.x;
    const int lane = tid & 31;
    const int w = tid >> 5;
    const int wm = (w & 1) * 64;
    const int wn = (w >> 1) * 64;

    const __half* Arow = A2 + ((long)z * aRows + brow) * (long)lda;
    const __half* Brow = B2 + ((long)z * bRows + bcol) * (long)ldb;

    const int nk = (CKLIM ? min(Ksrc, brow + 128) : Ksrc) / BKA;

    float acc[4][8][4];
#pragma unroll
    for (int i = 0; i < 4; ++i)
#pragma unroll
        for (int j = 0; j < 8; ++j)
#pragma unroll
            for (int u = 0; u < 4; ++u) acc[i][j][u] = 0.f;

    auto load_tile = [&](int t) {
        const int k0 = t * BKA;
        const uint32_t base = sb + (t % NSTG) * STAGE_B;
#pragma unroll
        for (int it = 0; it < 8; ++it) {
            const int idx = tid + it * 128;
            const int row = idx >> 3;
            const int ch  = idx & 7;
            const uint32_t off = row * (SSTR * 2) + ch * 16;
            cp16(base + off,         Arow + (long)row * lda + k0 + ch * 8);
            cp16(base + STG_B + off, Brow + (long)row * ldb + k0 + ch * 8);
        }
    };

    const int a_moff = lane & 15;
    const int a_koff = (lane >> 4) * 8;
    const int b_noff = (lane & 7) + (lane >> 4) * 8;
    const int b_koff = ((lane >> 3) & 1) * 8;

    load_tile(0); CP_COMMIT();
    load_tile(1); CP_COMMIT();
    CP_WAIT1();
    __syncthreads();

    for (int t = 0; t < nk; ++t) {
        if (t + 2 < nk) load_tile(t + 2);
        CP_COMMIT();

        const uint32_t abase = sb + (t % NSTG) * STAGE_B;
        const uint32_t bbase = abase + STG_B;
#pragma unroll
        for (int ks = 0; ks < 4; ++ks) {
            uint32_t a[4][4];
#pragma unroll
            for (int mi = 0; mi < 4; ++mi)
                ldmat4(a[mi], abase + (uint32_t)((wm + mi * 16 + a_moff) * (SSTR * 2)
                                                 + (ks * 16 + a_koff) * 2));
            uint32_t b[8][2];
#pragma unroll
            for (int np = 0; np < 4; ++np) {
                uint32_t bb[4];
                ldmat4(bb, bbase + (uint32_t)((wn + np * 16 + b_noff) * (SSTR * 2)
                                              + (ks * 16 + b_koff) * 2));
                b[np * 2][0] = bb[0]; b[np * 2][1] = bb[1];
                b[np * 2 + 1][0] = bb[2]; b[np * 2 + 1][1] = bb[3];
            }
#pragma unroll
            for (int mi = 0; mi < 4; ++mi)
#pragma unroll
                for (int nj = 0; nj < 8; ++nj)
                    mma16816(acc[mi][nj], a[mi], b[nj][0], b[nj][1]);
        }
        CP_WAIT1();
        __syncthreads();
    }

    // ---------------- epilogue ----------------
#pragma unroll
    for (int mi = 0; mi < 4; ++mi) {
#pragma unroll
        for (int half_ = 0; half_ < 2; ++half_) {
            const int r = brow + wm + mi * 16 + (lane >> 2) + half_ * 8;
#pragma unroll
            for (int nj = 0; nj < 8; ++nj) {
                const int c = bcol + wn + nj * 8 + 2 * (lane & 3);
                float v0 = acc[mi][nj][half_ * 2 + 0] * alpha;
                float v1 = acc[mi][nj][half_ * 2 + 1] * alpha;

                if (EPI == E_SC || EPI == E_FBR) {
                    if (EPI == E_FBR) {
                        v0 += bias[c]; v1 += bias[c + 1];
                        const float2 rv = *reinterpret_cast<const float2*>(
                            res + (long)r * Nsrc + c);
                        v0 += rv.x; v1 += rv.y;
                    }
                    float2 o; o.x = v0; o.y = v1;
                    *reinterpret_cast<float2*>(
                        (float*)Cp + ((long)z * cRows + r) * (long)Nsrc + c) = o;
                } else {
                    if (EPI == E_HB || EPI == E_HBR) { v0 += bias[c]; v1 += bias[c + 1]; }
                    if (EPI == E_HBR) { v0 = fmaxf(v0, 0.f); v1 = fmaxf(v1, 0.f); }
                    __half2 o2 = __floats2half2_rn(v0, v1);
                    *reinterpret_cast<__half2*>(
                        (__half*)Cp + ((long)z * cRows + r) * (long)Nsrc + c) = o2;
                }
            }
        }
    }
}

// ---------------- LayerNorm -> fp16 output (vectorized) ----------------
__global__ __launch_bounds__(256)
void layernorm_h(const float* __restrict__ x, const float* __restrict__ gamma,
                 const float* __restrict__ beta, __half* __restrict__ y)
{
    const long rowi = blockIdx.x;
    const int tid = threadIdx.x;
    const int lane = tid & 31;
    const int wid = tid >> 5;
    __shared__ float ws[8];

    const float4 xv = reinterpret_cast<const float4*>(x + rowi * Dc)[tid];

    float s = xv.x + xv.y + xv.z + xv.w;
#pragma unroll
    for (int o = 16; o > 0; o >>= 1) s += __shfl_xor_sync(0xffffffffu, s, o);
    if (lane == 0) ws[wid] = s;
    __syncthreads();
    float tot = 0.f;
#pragma unroll
    for (int i = 0; i < 8; ++i) tot += ws[i];
    const float mean = tot * (1.f / (float)Dc);
    __syncthreads();

    const float d0 = xv.x - mean, d1 = xv.y - mean, d2 = xv.z - mean, d3 = xv.w - mean;
    float v = d0 * d0 + d1 * d1 + d2 * d2 + d3 * d3;
#pragma unroll
    for (int o = 16; o > 0; o >>= 1) v += __shfl_xor_sync(0xffffffffu, v, o);
    if (lane == 0) ws[wid] = v;
    __syncthreads();
    float vtot = 0.f;
#pragma unroll
    for (int i = 0; i < 8; ++i) vtot += ws[i];
    const float var = vtot * (1.f / (float)(Dc - 1));   // ddof=1
    const float inv = 1.f / (sqrtf(var) + 1e-6f);       // eps on std

    const float4 gv = reinterpret_cast<const float4*>(gamma)[tid];
    const float4 bv = reinterpret_cast<const float4*>(beta)[tid];
    const float r0 = gv.x * d0 * inv + bv.x;
    const float r1 = gv.y * d1 * inv + bv.y;
    const float r2 = gv.z * d2 * inv + bv.z;
    const float r3 = gv.w * d3 * inv + bv.w;

    __half2* yr = reinterpret_cast<__half2*>(y + rowi * Dc);
    yr[2 * tid]     = __floats2half2_rn(r0, r1);
    yr[2 * tid + 1] = __floats2half2_rn(r2, r3);
}

// ---------------- causal softmax, single gmem read (smem row cache) --------
__global__ __launch_bounds__(256)
void softmax_h(const float* __restrict__ sc, __half* __restrict__ a)
{
    const int m = blockIdx.x;
    const int b = blockIdx.y;
    const float* row = sc + ((long)b * Sc + m) * (long)Sc;
    __half* orow = a + ((long)b * Sc + m) * (long)Sc;
    const int n = m + 1;
    const int tid = threadIdx.x;
    const int lane = tid & 31;
    const int wid = tid >> 5;

    __shared__ float sr[Sc];
    __shared__ float red[8];

    float lmax = -1e30f;
    for (int i = tid; i < n; i += 256) {
        const float v = row[i];
        sr[i] = v;
        lmax = fmaxf(lmax, v);
    }
#pragma unroll
    for (int o = 16; o > 0; o >>= 1)
        lmax = fmaxf(lmax, __shfl_xor_sync(0xffffffffu, lmax, o));
    if (lane == 0) red[wid] = lmax;
    __syncthreads();
    float gmax = -1e30f;
#pragma unroll
    for (int i = 0; i < 8; ++i) gmax = fmaxf(gmax, red[i]);
    __syncthreads();

    float lsum = 0.f;
    for (int i = tid; i < n; i += 256) {
        const float e = __expf(sr[i] - gmax);
        sr[i] = e;
        lsum += e;
    }
#pragma unroll
    for (int o = 16; o > 0; o >>= 1) lsum += __shfl_xor_sync(0xffffffffu, lsum, o);
    if (lane == 0) red[wid] = lsum;
    __syncthreads();
    float tot = 0.f;
#pragma unroll
    for (int i = 0; i < 8; ++i) tot += red[i];
    const float inv = 1.f / tot;

    for (int i = tid; i < n; i += 256)
        orow[i] = __float2half_rn(sr[i] * inv);
    const int lim = (m | 127);
    for (int i = n + tid; i <= lim; i += 256) orow[i] = __float2half_rn(0.f);
}

// ---------------- batched transpose f32 -> fp16 (all 6 weights, 1 launch) --
__global__ __launch_bounds__(256)
void trans_f2h6(const float* __restrict__ s0, const float* __restrict__ s1,
                const float* __restrict__ s2, const float* __restrict__ s3,
                const float* __restrict__ s4, const float* __restrict__ s5,
                __half* __restrict__ dstBase)
{
    const int zi = blockIdx.z;
    const float* src = (zi == 0) ? s0 : (zi == 1) ? s1 : (zi == 2) ? s2
                    : (zi == 3) ? s3 : (zi == 4) ? s4 : s5;
    __half* dst = dstBase + (size_t)zi * Dc * Dc;

    __shared__ float t[32][33];
    const int c0 = blockIdx.x * 32;
    const int r0 = blockIdx.y * 32;
    const int tx = threadIdx.x, ty = threadIdx.y;  // 32 x 8

#pragma unroll
    for (int i = 0; i < 4; ++i)
        t[ty + 8 * i][tx] = src[(long)(r0 + ty + 8 * i) * Dc + c0 + tx];
    __syncthreads();

#pragma unroll
    for (int i = 0; i < 4; ++i) {
        const int c = c0 + ty + 8 * i;
        const int r = r0 + tx;
        dst[(long)c * Dc + r] = __float2half_rn(t[tx][ty + 8 * i]);
    }
}

// ---------------- transpose fp16 -> fp16 (V slice of qkv), per batch -------
__global__ __launch_bounds__(256)
void trans_h2h(const __half* __restrict__ src, __half* __restrict__ dst,
               int R, int C, int srcStride, long srcBatch, long dstBatch)
{
    const int zb = blockIdx.z;
    src += (long)zb * srcBatch;
    dst += (long)zb * dstBatch;
    __shared__ __half t[32][34];
    const int c0 = blockIdx.x * 32;
    const int r0 = blockIdx.y * 32;
    const int tx = threadIdx.x, ty = threadIdx.y;

#pragma unroll
    for (int i = 0; i < 4; ++i)
        t[ty + 8 * i][tx] = src[(long)(r0 + ty + 8 * i) * srcStride + c0 + tx];
    __syncthreads();

#pragma unroll
    for (int i = 0; i < 4; ++i) {
        const int c = c0 + ty + 8 * i;
        const int r = r0 + tx;
        dst[(long)c * R + r] = t[tx][ty + 8 * i];
    }
}

// ---------------- bias concat ----------------
__global__ __launch_bounds__(256)
void concat_bias(const float* __restrict__ bq, const float* __restrict__ bk,
                 const float* __restrict__ bv, float* __restrict__ o)
{
    const int i = blockIdx.x * 256 + threadIdx.x;
    if (i < Dc) {
        o[i] = bq[i];
        o[Dc + i] = bk[i];
        o[2 * Dc + i] = bv[i];
    }
}

// ---------------------------------------------------------------------------
extern "C" void kernel_launch(void* const* d_in, const int* in_sizes, int n_in,
                              void* d_out, int out_size)
{
    const float* x   = (const float*)d_in[0];
    const float* wq  = (const float*)d_in[1];
    const float* bq  = (const float*)d_in[2];
    const float* wk  = (const float*)d_in[3];
    const float* bk  = (const float*)d_in[4];
    const float* wv  = (const float*)d_in[5];
    const float* bv  = (const float*)d_in[6];
    const float* wo  = (const float*)d_in[7];
    const float* bo  = (const float*)d_in[8];
    const float* w1  = (const float*)d_in[9];
    const float* b1  = (const float*)d_in[10];
    const float* w2  = (const float*)d_in[11];
    const float* b2  = (const float*)d_in[12];
    const float* g1  = (const float*)d_in[13];
    const float* be1 = (const float*)d_in[14];
    const float* g2  = (const float*)d_in[15];
    const float* be2 = (const float*)d_in[16];
    float* out = (float*)d_out;

    __half *xn, *qkv, *vt, *a, *ao, *m, *f, *wt;
    float *s, *h, *bqkv;
    cudaGetSymbolAddress((void**)&xn,  g_xn);
    cudaGetSymbolAddress((void**)&qkv, g_qkv);
    cudaGetSymbolAddress((void**)&vt,  g_vt);
    cudaGetSymbolAddress((void**)&s,   g_s);
    cudaGetSymbolAddress((void**)&a,   g_a);
    cudaGetSymbolAddress((void**)&ao,  g_ao);
    cudaGetSymbolAddress((void**)&h,   g_h);
    cudaGetSymbolAddress((void**)&m,   g_m);
    cudaGetSymbolAddress((void**)&f,   g_f);
    cudaGetSymbolAddress((void**)&wt,  g_wt);
    cudaGetSymbolAddress((void**)&bqkv, g_bqkv);

    __half* wot = wt + 3L * Dc * Dc;
    __half* w1t = wt + 4L * Dc * Dc;
    __half* w2t = wt + 5L * Dc * Dc;

    cudaFuncSetAttribute((const void*)tgemm<E_HB,  false, false>, cudaFuncAttributeMaxDynamicSharedMemorySize, SMEM_SZ);
    cudaFuncSetAttribute((const void*)tgemm<E_SC,  true,  false>, cudaFuncAttributeMaxDynamicSharedMemorySize, SMEM_SZ);
    cudaFuncSetAttribute((const void*)tgemm<E_H,   false, true >, cudaFuncAttributeMaxDynamicSharedMemorySize, SMEM_SZ);
    cudaFuncSetAttribute((const void*)tgemm<E_FBR, false, false>, cudaFuncAttributeMaxDynamicSharedMemorySize, SMEM_SZ);
    cudaFuncSetAttribute((const void*)tgemm<E_HBR, false, false>, cudaFuncAttributeMaxDynamicSharedMemorySize, SMEM_SZ);

    const float inv_sqrt_s = 1.0f / sqrtf((float)Sc);
    const dim3 tb(32, 8);
    const dim3 gW6(Dc / 32, Dc / 32, 6);
    const dim3 gV(Dc / 32, Sc / 32, Bc);
    const dim3 gQKV(D3 / 128, Mc / 128, 1);      // 24 x 64
    const dim3 gProj(Dc / 128, Mc / 128, 1);     // 8 x 64
    const dim3 gScore(Sc / 128, Sc / 128, Bc);   // 16 x 16 x 4
    const dim3 gAV(Dc / 128, Sc / 128, Bc);      // 8 x 16 x 4

    // all 6 weight transposes in one launch (QKV rows contiguous in g_wt)
    trans_f2h6<<<gW6, tb>>>(wq, wk, wv, wo, w1, w2, wt);
    concat_bias<<<4, 256>>>(bq, bk, bv, bqkv);

    // 1) LN1 -> xn (fp16)
    layernorm_h<<<Mc, 256>>>(x, g1, be1, xn);

    // 2) fused QKV projection: [M,1024] @ [3072,1024]^T -> [M,3072] fp16
    tgemm<E_HB, false, false><<<gQKV, 128, SMEM_SZ>>>(
        xn, wt, bqkv, nullptr, qkv, Dc, D3, 1.f, 0, 0, 0, Dc, Dc);

    // 3) v slice -> vt (transpose per batch)
    trans_h2h<<<gV, tb>>>(qkv + 2 * Dc, vt, Sc, Dc, D3,
                          (long)Sc * D3, (long)Dc * Sc);

    // 4) scores = (q k^T)/sqrt(S), causal tiles skipped (f32 out)
    tgemm<E_SC, true, false><<<gScore, 128, SMEM_SZ>>>(
        qkv, qkv + Dc, nullptr, nullptr, s, Dc, Sc, inv_sqrt_s,
        Sc, Sc, Sc, D3, D3);

    // 5) softmax -> a (fp16 + zero pad)
    softmax_h<<<dim3(Sc, Bc), 256>>>(s, a);

    // 6) attn @ V with block-K limit -> ao (fp16)
    tgemm<E_H, false, true><<<gAV, 128, SMEM_SZ>>>(
        a, vt, nullptr, nullptr, ao, Sc, Dc, 1.f, Sc, Dc, Sc, Sc, Sc);

    // 7) h = ao @ wo + bo + x (f32)
    tgemm<E_FBR, false, false><<<gProj, 128, SMEM_SZ>>>(
        ao, wot, bo, x, h, Dc, Dc, 1.f, 0, 0, 0, Dc, Dc);

    // 8) LN2 -> m (fp16)
    layernorm_h<<<Mc, 256>>>(h, g2, be2, m);

    // 9) f = relu(m @ w1 + b1) (fp16)
    tgemm<E_HBR, false, false><<<gProj, 128, SMEM_SZ>>>(
        m, w1t, b1, nullptr, f, Dc, Dc, 1.f, 0, 0, 0, Dc, Dc);

    // 10) out = f @ w2 + b2 + h (f32)
    tgemm<E_FBR, false, false><<<gProj, 128, SMEM_SZ>>>(
        f, w2t, b2, h, out, Dc, Dc, 1.f, 0, 0, 0, Dc, Dc);
}

// round 13
// speedup vs baseline: 1.5999x; 1.0023x over previous
#include <cuda_runtime.h>
#include <cuda_fp16.h>
#include <math.h>
#include <stdint.h>

// ---------------- problem shape ----------------
#define Bc 4
#define Sc 2048
#define Dc 1024
#define Mc (Bc * Sc)
#define D3 (3 * Dc)

// ---------------- scratch (device globals; no allocation allowed) ----------
__device__ __align__(256) __half g_xn  [(size_t)Mc * Dc];
__device__ __align__(256) __half g_qkv [(size_t)Mc * D3];
__device__ __align__(256) __half g_vt  [(size_t)Bc * Dc * Sc];
__device__ __align__(256) float  g_s   [(size_t)Bc * Sc * Sc];
__device__ __align__(256) __half g_a   [(size_t)Bc * Sc * Sc];
__device__ __align__(256) __half g_ao  [(size_t)Mc * Dc];
__device__ __align__(256) float  g_h   [(size_t)Mc * Dc];
__device__ __align__(256) __half g_m   [(size_t)Mc * Dc];
__device__ __align__(256) __half g_f   [(size_t)Mc * Dc];
__device__ __align__(256) __half g_wt  [6][(size_t)Dc * Dc];
__device__ __align__(256) float  g_bqkv[D3];

// ---------------- PTX helpers ----------------
__device__ __forceinline__ uint32_t s2u(const void* p) {
    uint32_t a;
    asm("{ .reg .u64 t; cvta.to.shared.u64 t, %1; cvt.u32.u64 %0, t; }"
        : "=r"(a) : "l"(p));
    return a;
}
__device__ __forceinline__ void cp16(uint32_t s, const void* g) {
    asm volatile("cp.async.cg.shared.global [%0], [%1], 16;" :: "r"(s), "l"(g));
}
#define CP_COMMIT() asm volatile("cp.async.commit_group;" ::: "memory")
#define CP_WAIT1()  asm volatile("cp.async.wait_group 1;" ::: "memory")

__device__ __forceinline__ void ldmat4(uint32_t (&r)[4], uint32_t addr) {
    asm volatile("ldmatrix.sync.aligned.m8n8.x4.shared.b16 {%0,%1,%2,%3}, [%4];"
                 : "=r"(r[0]), "=r"(r[1]), "=r"(r[2]), "=r"(r[3]) : "r"(addr));
}
__device__ __forceinline__ void mma16816(float (&d)[4], const uint32_t (&a)[4],
                                         const uint32_t b0, const uint32_t b1) {
    asm volatile(
        "mma.sync.aligned.m16n8k16.row.col.f32.f16.f16.f32 "
        "{%0,%1,%2,%3},{%4,%5,%6,%7},{%8,%9},{%0,%1,%2,%3};"
        : "+f"(d[0]), "+f"(d[1]), "+f"(d[2]), "+f"(d[3])
        : "r"(a[0]), "r"(a[1]), "r"(a[2]), "r"(a[3]), "r"(b0), "r"(b1));
}

// ---------------- fp16 mma GEMM (64x64 warp tile, 3-stage, BK=64) ----------
// C = alpha * A[.,K] (x) B[.,K]^T    (both operands row-major over K, strided)
#define E_SC  0
#define E_FBR 2
#define E_H   7
#define E_HB  8
#define E_HBR 9

#define BKA 64                         // K per stage (fp16)
#define SSTR 72                        // padded smem row stride in halves (144 B)
#define STG_B (128 * SSTR * 2)         // one operand tile = 18432 B
#define STAGE_B (2 * STG_B)            // A+B per stage   = 36864 B
#define NSTG 3
#define SMEM_SZ (NSTG * STAGE_B)       // 110592 B

template <int EPI, bool CSKIP, bool CKLIM>
__global__ __launch_bounds__(128, 2)
void tgemm(const __half* __restrict__ A2, const __half* __restrict__ B2,
           const float* __restrict__ bias, const float* __restrict__ res,
           void* __restrict__ Cp, int Ksrc, int Nsrc, float alpha,
           long aRows, long bRows, long cRows, int lda, int ldb)
{
    const int brow = blockIdx.y * 128;
    const int bcol = blockIdx.x * 128;
    if (CSKIP && bcol > brow + 127) return;
    const int z = blockIdx.z;

    extern __shared__ __align__(16) char smem[];
    const uint32_t sb = s2u(smem);

    const int tid = threadIdx.x;
    const int lane = tid & 31;
    const int w = tid >> 5;
    const int wm = (w & 1) * 64;
    const int wn = (w >> 1) * 64;

    const __half* Arow = A2 + ((long)z * aRows + brow) * (long)lda;
    const __half* Brow = B2 + ((long)z * bRows + bcol) * (long)ldb;

    const int nk = (CKLIM ? min(Ksrc, brow + 128) : Ksrc) / BKA;

    float acc[4][8][4];
#pragma unroll
    for (int i = 0; i < 4; ++i)
#pragma unroll
        for (int j = 0; j < 8; ++j)
#pragma unroll
            for (int u = 0; u < 4; ++u) acc[i][j][u] = 0.f;

    auto load_tile = [&](int t) {
        const int k0 = t * BKA;
        const uint32_t base = sb + (t % NSTG) * STAGE_B;
#pragma unroll
        for (int it = 0; it < 8; ++it) {
            const int idx = tid + it * 128;
            const int row = idx >> 3;
            const int ch  = idx & 7;
            const uint32_t off = row * (SSTR * 2) + ch * 16;
            cp16(base + off,         Arow + (long)row * lda + k0 + ch * 8);
            cp16(base + STG_B + off, Brow + (long)row * ldb + k0 + ch * 8);
        }
    };

    const int a_moff = lane & 15;
    const int a_koff = (lane >> 4) * 8;
    const int b_noff = (lane & 7) + (lane >> 4) * 8;
    const int b_koff = ((lane >> 3) & 1) * 8;

    load_tile(0); CP_COMMIT();
    load_tile(1); CP_COMMIT();
    CP_WAIT1();
    __syncthreads();

    for (int t = 0; t < nk; ++t) {
        if (t + 2 < nk) load_tile(t + 2);
        CP_COMMIT();

        const uint32_t abase = sb + (t % NSTG) * STAGE_B;
        const uint32_t bbase = abase + STG_B;

        // fragment addresses
        auto addrA = [&](int ks, int mi) -> uint32_t {
            return abase + (uint32_t)((wm + mi * 16 + a_moff) * (SSTR * 2)
                                      + (ks * 16 + a_koff) * 2);
        };
        auto addrB = [&](int ks, int np) -> uint32_t {
            return bbase + (uint32_t)((wn + np * 16 + b_noff) * (SSTR * 2)
                                      + (ks * 16 + b_koff) * 2);
        };

        // software-pipelined fragments: A double-buffered across ks,
        // B rolling ping-pong across np.
        uint32_t afr[2][4][4];
#pragma unroll
        for (int mi = 0; mi < 4; ++mi) ldmat4(afr[0][mi], addrA(0, mi));

#pragma unroll
        for (int ks = 0; ks < 4; ++ks) {
            const int cur = ks & 1;
            const int nxt = cur ^ 1;
            uint32_t bb[2][4];
            ldmat4(bb[0], addrB(ks, 0));
#pragma unroll
            for (int np = 0; np < 4; ++np) {
                const int pc = np & 1;
                const int pn = pc ^ 1;
                if (np < 3) ldmat4(bb[pn], addrB(ks, np + 1));
                if (ks < 3) {
                    if (np == 2) {
                        ldmat4(afr[nxt][0], addrA(ks + 1, 0));
                        ldmat4(afr[nxt][1], addrA(ks + 1, 1));
                    }
                    if (np == 3) {
                        ldmat4(afr[nxt][2], addrA(ks + 1, 2));
                        ldmat4(afr[nxt][3], addrA(ks + 1, 3));
                    }
                }
#pragma unroll
                for (int mi = 0; mi < 4; ++mi) {
                    mma16816(acc[mi][np * 2],     afr[cur][mi], bb[pc][0], bb[pc][1]);
                    mma16816(acc[mi][np * 2 + 1], afr[cur][mi], bb[pc][2], bb[pc][3]);
                }
            }
        }
        CP_WAIT1();
        __syncthreads();
    }

    // ---------------- epilogue ----------------
#pragma unroll
    for (int mi = 0; mi < 4; ++mi) {
#pragma unroll
        for (int half_ = 0; half_ < 2; ++half_) {
            const int r = brow + wm + mi * 16 + (lane >> 2) + half_ * 8;
#pragma unroll
            for (int nj = 0; nj < 8; ++nj) {
                const int c = bcol + wn + nj * 8 + 2 * (lane & 3);
                float v0 = acc[mi][nj][half_ * 2 + 0] * alpha;
                float v1 = acc[mi][nj][half_ * 2 + 1] * alpha;

                if (EPI == E_SC || EPI == E_FBR) {
                    if (EPI == E_FBR) {
                        v0 += bias[c]; v1 += bias[c + 1];
                        const float2 rv = *reinterpret_cast<const float2*>(
                            res + (long)r * Nsrc + c);
                        v0 += rv.x; v1 += rv.y;
                    }
                    float2 o; o.x = v0; o.y = v1;
                    *reinterpret_cast<float2*>(
                        (float*)Cp + ((long)z * cRows + r) * (long)Nsrc + c) = o;
                } else {
                    if (EPI == E_HB || EPI == E_HBR) { v0 += bias[c]; v1 += bias[c + 1]; }
                    if (EPI == E_HBR) { v0 = fmaxf(v0, 0.f); v1 = fmaxf(v1, 0.f); }
                    __half2 o2 = __floats2half2_rn(v0, v1);
                    *reinterpret_cast<__half2*>(
                        (__half*)Cp + ((long)z * cRows + r) * (long)Nsrc + c) = o2;
                }
            }
        }
    }
}

// ---------------- LayerNorm -> fp16 output (vectorized) ----------------
__global__ __launch_bounds__(256)
void layernorm_h(const float* __restrict__ x, const float* __restrict__ gamma,
                 const float* __restrict__ beta, __half* __restrict__ y)
{
    const long rowi = blockIdx.x;
    const int tid = threadIdx.x;
    const int lane = tid & 31;
    const int wid = tid >> 5;
    __shared__ float ws[8];

    const float4 xv = reinterpret_cast<const float4*>(x + rowi * Dc)[tid];

    float s = xv.x + xv.y + xv.z + xv.w;
#pragma unroll
    for (int o = 16; o > 0; o >>= 1) s += __shfl_xor_sync(0xffffffffu, s, o);
    if (lane == 0) ws[wid] = s;
    __syncthreads();
    float tot = 0.f;
#pragma unroll
    for (int i = 0; i < 8; ++i) tot += ws[i];
    const float mean = tot * (1.f / (float)Dc);
    __syncthreads();

    const float d0 = xv.x - mean, d1 = xv.y - mean, d2 = xv.z - mean, d3 = xv.w - mean;
    float v = d0 * d0 + d1 * d1 + d2 * d2 + d3 * d3;
#pragma unroll
    for (int o = 16; o > 0; o >>= 1) v += __shfl_xor_sync(0xffffffffu, v, o);
    if (lane == 0) ws[wid] = v;
    __syncthreads();
    float vtot = 0.f;
#pragma unroll
    for (int i = 0; i < 8; ++i) vtot += ws[i];
    const float var = vtot * (1.f / (float)(Dc - 1));   // ddof=1
    const float inv = 1.f / (sqrtf(var) + 1e-6f);       // eps on std

    const float4 gv = reinterpret_cast<const float4*>(gamma)[tid];
    const float4 bv = reinterpret_cast<const float4*>(beta)[tid];
    const float r0 = gv.x * d0 * inv + bv.x;
    const float r1 = gv.y * d1 * inv + bv.y;
    const float r2 = gv.z * d2 * inv + bv.z;
    const float r3 = gv.w * d3 * inv + bv.w;

    __half2* yr = reinterpret_cast<__half2*>(y + rowi * Dc);
    yr[2 * tid]     = __floats2half2_rn(r0, r1);
    yr[2 * tid + 1] = __floats2half2_rn(r2, r3);
}

// ---------------- causal softmax, single gmem read (smem row cache) --------
__global__ __launch_bounds__(256)
void softmax_h(const float* __restrict__ sc, __half* __restrict__ a)
{
    const int m = blockIdx.x;
    const int b = blockIdx.y;
    const float* row = sc + ((long)b * Sc + m) * (long)Sc;
    __half* orow = a + ((long)b * Sc + m) * (long)Sc;
    const int n = m + 1;
    const int tid = threadIdx.x;
    const int lane = tid & 31;
    const int wid = tid >> 5;

    __shared__ float sr[Sc];
    __shared__ float red[8];

    float lmax = -1e30f;
    for (int i = tid; i < n; i += 256) {
        const float v = row[i];
        sr[i] = v;
        lmax = fmaxf(lmax, v);
    }
#pragma unroll
    for (int o = 16; o > 0; o >>= 1)
        lmax = fmaxf(lmax, __shfl_xor_sync(0xffffffffu, lmax, o));
    if (lane == 0) red[wid] = lmax;
    __syncthreads();
    float gmax = -1e30f;
#pragma unroll
    for (int i = 0; i < 8; ++i) gmax = fmaxf(gmax, red[i]);
    __syncthreads();

    float lsum = 0.f;
    for (int i = tid; i < n; i += 256) {
        const float e = __expf(sr[i] - gmax);
        sr[i] = e;
        lsum += e;
    }
#pragma unroll
    for (int o = 16; o > 0; o >>= 1) lsum += __shfl_xor_sync(0xffffffffu, lsum, o);
    if (lane == 0) red[wid] = lsum;
    __syncthreads();
    float tot = 0.f;
#pragma unroll
    for (int i = 0; i < 8; ++i) tot += red[i];
    const float inv = 1.f / tot;

    for (int i = tid; i < n; i += 256)
        orow[i] = __float2half_rn(sr[i] * inv);
    const int lim = (m | 127);
    for (int i = n + tid; i <= lim; i += 256) orow[i] = __float2half_rn(0.f);
}

// ---------------- batched transpose f32 -> fp16 (all 6 weights, 1 launch) --
__global__ __launch_bounds__(256)
void trans_f2h6(const float* __restrict__ s0, const float* __restrict__ s1,
                const float* __restrict__ s2, const float* __restrict__ s3,
                const float* __restrict__ s4, const float* __restrict__ s5,
                __half* __restrict__ dstBase)
{
    const int zi = blockIdx.z;
    const float* src = (zi == 0) ? s0 : (zi == 1) ? s1 : (zi == 2) ? s2
                    : (zi == 3) ? s3 : (zi == 4) ? s4 : s5;
    __half* dst = dstBase + (size_t)zi * Dc * Dc;

    __shared__ float t[32][33];
    const int c0 = blockIdx.x * 32;
    const int r0 = blockIdx.y * 32;
    const int tx = threadIdx.x, ty = threadIdx.y;  // 32 x 8

#pragma unroll
    for (int i = 0; i < 4; ++i)
        t[ty + 8 * i][tx] = src[(long)(r0 + ty + 8 * i) * Dc + c0 + tx];
    __syncthreads();

#pragma unroll
    for (int i = 0; i < 4; ++i) {
        const int c = c0 + ty + 8 * i;
        const int r = r0 + tx;
        dst[(long)c * Dc + r] = __float2half_rn(t[tx][ty + 8 * i]);
    }
}

// ---------------- transpose fp16 -> fp16 (V slice of qkv), per batch -------
__global__ __launch_bounds__(256)
void trans_h2h(const __half* __restrict__ src, __half* __restrict__ dst,
               int R, int C, int srcStride, long srcBatch, long dstBatch)
{
    const int zb = blockIdx.z;
    src += (long)zb * srcBatch;
    dst += (long)zb * dstBatch;
    __shared__ __half t[32][34];
    const int c0 = blockIdx.x * 32;
    const int r0 = blockIdx.y * 32;
    const int tx = threadIdx.x, ty = threadIdx.y;

#pragma unroll
    for (int i = 0; i < 4; ++i)
        t[ty + 8 * i][tx] = src[(long)(r0 + ty + 8 * i) * srcStride + c0 + tx];
    __syncthreads();

#pragma unroll
    for (int i = 0; i < 4; ++i) {
        const int c = c0 + ty + 8 * i;
        const int r = r0 + tx;
        dst[(long)c * R + r] = t[tx][ty + 8 * i];
    }
}

// ---------------- bias concat ----------------
__global__ __launch_bounds__(256)
void concat_bias(const float* __restrict__ bq, const float* __restrict__ bk,
                 const float* __restrict__ bv, float* __restrict__ o)
{
    const int i = blockIdx.x * 256 + threadIdx.x;
    if (i < Dc) {
        o[i] = bq[i];
        o[Dc + i] = bk[i];
        o[2 * Dc + i] = bv[i];
    }
}

// ---------------------------------------------------------------------------
extern "C" void kernel_launch(void* const* d_in, const int* in_sizes, int n_in,
                              void* d_out, int out_size)
{
    const float* x   = (const float*)d_in[0];
    const float* wq  = (const float*)d_in[1];
    const float* bq  = (const float*)d_in[2];
    const float* wk  = (const float*)d_in[3];
    const float* bk  = (const float*)d_in[4];
    const float* wv  = (const float*)d_in[5];
    const float* bv  = (const float*)d_in[6];
    const float* wo  = (const float*)d_in[7];
    const float* bo  = (const float*)d_in[8];
    const float* w1  = (const float*)d_in[9];
    const float* b1  = (const float*)d_in[10];
    const float* w2  = (const float*)d_in[11];
    const float* b2  = (const float*)d_in[12];
    const float* g1  = (const float*)d_in[13];
    const float* be1 = (const float*)d_in[14];
    const float* g2  = (const float*)d_in[15];
    const float* be2 = (const float*)d_in[16];
    float* out = (float*)d_out;

    __half *xn, *qkv, *vt, *a, *ao, *m, *f, *wt;
    float *s, *h, *bqkv;
    cudaGetSymbolAddress((void**)&xn,  g_xn);
    cudaGetSymbolAddress((void**)&qkv, g_qkv);
    cudaGetSymbolAddress((void**)&vt,  g_vt);
    cudaGetSymbolAddress((void**)&s,   g_s);
    cudaGetSymbolAddress((void**)&a,   g_a);
    cudaGetSymbolAddress((void**)&ao,  g_ao);
    cudaGetSymbolAddress((void**)&h,   g_h);
    cudaGetSymbolAddress((void**)&m,   g_m);
    cudaGetSymbolAddress((void**)&f,   g_f);
    cudaGetSymbolAddress((void**)&wt,  g_wt);
    cudaGetSymbolAddress((void**)&bqkv, g_bqkv);

    __half* wot = wt + 3L * Dc * Dc;
    __half* w1t = wt + 4L * Dc * Dc;
    __half* w2t = wt + 5L * Dc * Dc;

    cudaFuncSetAttribute((const void*)tgemm<E_HB,  false, false>, cudaFuncAttributeMaxDynamicSharedMemorySize, SMEM_SZ);
    cudaFuncSetAttribute((const void*)tgemm<E_SC,  true,  false>, cudaFuncAttributeMaxDynamicSharedMemorySize, SMEM_SZ);
    cudaFuncSetAttribute((const void*)tgemm<E_H,   false, true >, cudaFuncAttributeMaxDynamicSharedMemorySize, SMEM_SZ);
    cudaFuncSetAttribute((const void*)tgemm<E_FBR, false, false>, cudaFuncAttributeMaxDynamicSharedMemorySize, SMEM_SZ);
    cudaFuncSetAttribute((const void*)tgemm<E_HBR, false, false>, cudaFuncAttributeMaxDynamicSharedMemorySize, SMEM_SZ);

    const float inv_sqrt_s = 1.0f / sqrtf((float)Sc);
    const dim3 tb(32, 8);
    const dim3 gW6(Dc / 32, Dc / 32, 6);
    const dim3 gV(Dc / 32, Sc / 32, Bc);
    const dim3 gQKV(D3 / 128, Mc / 128, 1);      // 24 x 64
    const dim3 gProj(Dc / 128, Mc / 128, 1);     // 8 x 64
    const dim3 gScore(Sc / 128, Sc / 128, Bc);   // 16 x 16 x 4
    const dim3 gAV(Dc / 128, Sc / 128, Bc);      // 8 x 16 x 4

    // all 6 weight transposes in one launch (QKV rows contiguous in g_wt)
    trans_f2h6<<<gW6, tb>>>(wq, wk, wv, wo, w1, w2, wt);
    concat_bias<<<4, 256>>>(bq, bk, bv, bqkv);

    // 1) LN1 -> xn (fp16)
    layernorm_h<<<Mc, 256>>>(x, g1, be1, xn);

    // 2) fused QKV projection: [M,1024] @ [3072,1024]^T -> [M,3072] fp16
    tgemm<E_HB, false, false><<<gQKV, 128, SMEM_SZ>>>(
        xn, wt, bqkv, nullptr, qkv, Dc, D3, 1.f, 0, 0, 0, Dc, Dc);

    // 3) v slice -> vt (transpose per batch)
    trans_h2h<<<gV, tb>>>(qkv + 2 * Dc, vt, Sc, Dc, D3,
                          (long)Sc * D3, (long)Dc * Sc);

    // 4) scores = (q k^T)/sqrt(S), causal tiles skipped (f32 out)
    tgemm<E_SC, true, false><<<gScore, 128, SMEM_SZ>>>(
        qkv, qkv + Dc, nullptr, nullptr, s, Dc, Sc, inv_sqrt_s,
        Sc, Sc, Sc, D3, D3);

    // 5) softmax -> a (fp16 + zero pad)
    softmax_h<<<dim3(Sc, Bc), 256>>>(s, a);

    // 6) attn @ V with block-K limit -> ao (fp16)
    tgemm<E_H, false, true><<<gAV, 128, SMEM_SZ>>>(
        a, vt, nullptr, nullptr, ao, Sc, Dc, 1.f, Sc, Dc, Sc, Sc, Sc);

    // 7) h = ao @ wo + bo + x (f32)
    tgemm<E_FBR, false, false><<<gProj, 128, SMEM_SZ>>>(
        ao, wot, bo, x, h, Dc, Dc, 1.f, 0, 0, 0, Dc, Dc);

    // 8) LN2 -> m (fp16)
    layernorm_h<<<Mc, 256>>>(h, g2, be2, m);

    // 9) f = relu(m @ w1 + b1) (fp16)
    tgemm<E_HBR, false, false><<<gProj, 128, SMEM_SZ>>>(
        m, w1t, b1, nullptr, f, Dc, Dc, 1.f, 0, 0, 0, Dc, Dc);

    // 10) out = f @ w2 + b2 + h (f32)
    tgemm<E_FBR, false, false><<<gProj, 128, SMEM_SZ>>>(
        f, w2t, b2, h, out, Dc, Dc, 1.f, 0, 0, 0, Dc, Dc);
}

// round 15
// speedup vs baseline: 1.6024x; 1.0016x over previous
#include <cuda_runtime.h>
#include <cuda_fp16.h>
#include <math.h>
#include <stdint.h>

// ---------------- problem shape ----------------
#define Bc 4
#define Sc 2048
#define Dc 1024
#define Mc (Bc * Sc)
#define D3 (3 * Dc)

// ---------------- scratch (device globals; no allocation allowed) ----------
__device__ __align__(256) __half g_xn  [(size_t)Mc * Dc];
__device__ __align__(256) __half g_qkv [(size_t)Mc * D3];
__device__ __align__(256) __half g_vt  [(size_t)Bc * Dc * Sc];
__device__ __align__(256) __half g_s   [(size_t)Bc * Sc * Sc];
__device__ __align__(256) __half g_a   [(size_t)Bc * Sc * Sc];
__device__ __align__(256) __half g_ao  [(size_t)Mc * Dc];
__device__ __align__(256) float  g_h   [(size_t)Mc * Dc];
__device__ __align__(256) __half g_m   [(size_t)Mc * Dc];
__device__ __align__(256) __half g_f   [(size_t)Mc * Dc];
__device__ __align__(256) __half g_wt  [6][(size_t)Dc * Dc];
__device__ __align__(256) float  g_bqkv[D3];

// ---------------- PTX helpers ----------------
__device__ __forceinline__ uint32_t s2u(const void* p) {
    uint32_t a;
    asm("{ .reg .u64 t; cvta.to.shared.u64 t, %1; cvt.u32.u64 %0, t; }"
        : "=r"(a) : "l"(p));
    return a;
}
__device__ __forceinline__ void cp16(uint32_t s, const void* g) {
    asm volatile("cp.async.cg.shared.global [%0], [%1], 16;" :: "r"(s), "l"(g));
}
#define CP_COMMIT() asm volatile("cp.async.commit_group;" ::: "memory")
#define CP_WAIT1()  asm volatile("cp.async.wait_group 1;" ::: "memory")

__device__ __forceinline__ void ldmat4(uint32_t (&r)[4], uint32_t addr) {
    asm volatile("ldmatrix.sync.aligned.m8n8.x4.shared.b16 {%0,%1,%2,%3}, [%4];"
                 : "=r"(r[0]), "=r"(r[1]), "=r"(r[2]), "=r"(r[3]) : "r"(addr));
}
__device__ __forceinline__ void mma16816(float (&d)[4], const uint32_t (&a)[4],
                                         const uint32_t b0, const uint32_t b1) {
    asm volatile(
        "mma.sync.aligned.m16n8k16.row.col.f32.f16.f16.f32 "
        "{%0,%1,%2,%3},{%4,%5,%6,%7},{%8,%9},{%0,%1,%2,%3};"
        : "+f"(d[0]), "+f"(d[1]), "+f"(d[2]), "+f"(d[3])
        : "r"(a[0]), "r"(a[1]), "r"(a[2]), "r"(a[3]), "r"(b0), "r"(b1));
}

// ---------------- fp16 mma GEMM (64x64 warp tile, 3-stage, BK=64) ----------
// C = alpha * A[.,K] (x) B[.,K]^T    (both operands row-major over K, strided)
#define E_FBR 2
#define E_H   7
#define E_HB  8
#define E_HBR 9

#define BKA 64                         // K per stage (fp16)
#define SSTR 72                        // padded smem row stride in halves (144 B)
#define STG_B (128 * SSTR * 2)         // one operand tile = 18432 B
#define STAGE_B (2 * STG_B)            // A+B per stage   = 36864 B
#define NSTG 3
#define SMEM_SZ (NSTG * STAGE_B)       // 110592 B

template <int EPI, bool CSKIP, bool CKLIM>
__global__ __launch_bounds__(128, 2)
void tgemm(const __half* __restrict__ A2, const __half* __restrict__ B2,
           const float* __restrict__ bias, const float* __restrict__ res,
           void* __restrict__ Cp, int Ksrc, int Nsrc, float alpha,
           long aRows, long bRows, long cRows, int lda, int ldb)
{
    const int brow = blockIdx.y * 128;
    const int bcol = blockIdx.x * 128;
    if (CSKIP && bcol > brow + 127) return;
    const int z = blockIdx.z;

    extern __shared__ __align__(16) char smem[];
    const uint32_t sb = s2u(smem);

    const int tid = threadIdx.x;
    const int lane = tid & 31;
    const int w = tid >> 5;
    const int wm = (w & 1) * 64;
    const int wn = (w >> 1) * 64;

    const __half* Arow = A2 + ((long)z * aRows + brow) * (long)lda;
    const __half* Brow = B2 + ((long)z * bRows + bcol) * (long)ldb;

    const int nk = (CKLIM ? min(Ksrc, brow + 128) : Ksrc) / BKA;

    float acc[4][8][4];
#pragma unroll
    for (int i = 0; i < 4; ++i)
#pragma unroll
        for (int j = 0; j < 8; ++j)
#pragma unroll
            for (int u = 0; u < 4; ++u) acc[i][j][u] = 0.f;

    auto load_tile = [&](int t) {
        const int k0 = t * BKA;
        const uint32_t base = sb + (t % NSTG) * STAGE_B;
#pragma unroll
        for (int it = 0; it < 8; ++it) {
            const int idx = tid + it * 128;
            const int row = idx >> 3;
            const int ch  = idx & 7;
            const uint32_t off = row * (SSTR * 2) + ch * 16;
            cp16(base + off,         Arow + (long)row * lda + k0 + ch * 8);
            cp16(base + STG_B + off, Brow + (long)row * ldb + k0 + ch * 8);
        }
    };

    const int a_moff = lane & 15;
    const int a_koff = (lane >> 4) * 8;
    const int b_noff = (lane & 7) + (lane >> 4) * 8;
    const int b_koff = ((lane >> 3) & 1) * 8;

    load_tile(0); CP_COMMIT();
    load_tile(1); CP_COMMIT();
    CP_WAIT1();
    __syncthreads();

    for (int t = 0; t < nk; ++t) {
        if (t + 2 < nk) load_tile(t + 2);
        CP_COMMIT();

        const uint32_t abase = sb + (t % NSTG) * STAGE_B;
        const uint32_t bbase = abase + STG_B;
#pragma unroll
        for (int ks = 0; ks < 4; ++ks) {
            uint32_t a[4][4];
#pragma unroll
            for (int mi = 0; mi < 4; ++mi)
                ldmat4(a[mi], abase + (uint32_t)((wm + mi * 16 + a_moff) * (SSTR * 2)
                                                 + (ks * 16 + a_koff) * 2));
            uint32_t b[8][2];
#pragma unroll
            for (int np = 0; np < 4; ++np) {
                uint32_t bb[4];
                ldmat4(bb, bbase + (uint32_t)((wn + np * 16 + b_noff) * (SSTR * 2)
                                              + (ks * 16 + b_koff) * 2));
                b[np * 2][0] = bb[0]; b[np * 2][1] = bb[1];
                b[np * 2 + 1][0] = bb[2]; b[np * 2 + 1][1] = bb[3];
            }
#pragma unroll
            for (int mi = 0; mi < 4; ++mi)
#pragma unroll
                for (int nj = 0; nj < 8; ++nj)
                    mma16816(acc[mi][nj], a[mi], b[nj][0], b[nj][1]);
        }
        CP_WAIT1();
        __syncthreads();
    }

    // ---------------- epilogue ----------------
#pragma unroll
    for (int mi = 0; mi < 4; ++mi) {
#pragma unroll
        for (int half_ = 0; half_ < 2; ++half_) {
            const int r = brow + wm + mi * 16 + (lane >> 2) + half_ * 8;
#pragma unroll
            for (int nj = 0; nj < 8; ++nj) {
                const int c = bcol + wn + nj * 8 + 2 * (lane & 3);
                float v0 = acc[mi][nj][half_ * 2 + 0] * alpha;
                float v1 = acc[mi][nj][half_ * 2 + 1] * alpha;

                if (EPI == E_FBR) {
                    v0 += bias[c]; v1 += bias[c + 1];
                    const float2 rv = *reinterpret_cast<const float2*>(
                        res + (long)r * Nsrc + c);
                    v0 += rv.x; v1 += rv.y;
                    float2 o; o.x = v0; o.y = v1;
                    *reinterpret_cast<float2*>(
                        (float*)Cp + ((long)z * cRows + r) * (long)Nsrc + c) = o;
                } else {
                    if (EPI == E_HB || EPI == E_HBR) { v0 += bias[c]; v1 += bias[c + 1]; }
                    if (EPI == E_HBR) { v0 = fmaxf(v0, 0.f); v1 = fmaxf(v1, 0.f); }
                    __half2 o2 = __floats2half2_rn(v0, v1);
                    *reinterpret_cast<__half2*>(
                        (__half*)Cp + ((long)z * cRows + r) * (long)Nsrc + c) = o2;
                }
            }
        }
    }
}

// ---------------- LayerNorm -> fp16 output (vectorized) ----------------
__global__ __launch_bounds__(256)
void layernorm_h(const float* __restrict__ x, const float* __restrict__ gamma,
                 const float* __restrict__ beta, __half* __restrict__ y)
{
    const long rowi = blockIdx.x;
    const int tid = threadIdx.x;
    const int lane = tid & 31;
    const int wid = tid >> 5;
    __shared__ float ws[8];

    const float4 xv = reinterpret_cast<const float4*>(x + rowi * Dc)[tid];

    float s = xv.x + xv.y + xv.z + xv.w;
#pragma unroll
    for (int o = 16; o > 0; o >>= 1) s += __shfl_xor_sync(0xffffffffu, s, o);
    if (lane == 0) ws[wid] = s;
    __syncthreads();
    float tot = 0.f;
#pragma unroll
    for (int i = 0; i < 8; ++i) tot += ws[i];
    const float mean = tot * (1.f / (float)Dc);
    __syncthreads();

    const float d0 = xv.x - mean, d1 = xv.y - mean, d2 = xv.z - mean, d3 = xv.w - mean;
    float v = d0 * d0 + d1 * d1 + d2 * d2 + d3 * d3;
#pragma unroll
    for (int o = 16; o > 0; o >>= 1) v += __shfl_xor_sync(0xffffffffu, v, o);
    if (lane == 0) ws[wid] = v;
    __syncthreads();
    float vtot = 0.f;
#pragma unroll
    for (int i = 0; i < 8; ++i) vtot += ws[i];
    const float var = vtot * (1.f / (float)(Dc - 1));   // ddof=1
    const float inv = 1.f / (sqrtf(var) + 1e-6f);       // eps on std

    const float4 gv = reinterpret_cast<const float4*>(gamma)[tid];
    const float4 bv = reinterpret_cast<const float4*>(beta)[tid];
    const float r0 = gv.x * d0 * inv + bv.x;
    const float r1 = gv.y * d1 * inv + bv.y;
    const float r2 = gv.z * d2 * inv + bv.z;
    const float r3 = gv.w * d3 * inv + bv.w;

    __half2* yr = reinterpret_cast<__half2*>(y + rowi * Dc);
    yr[2 * tid]     = __floats2half2_rn(r0, r1);
    yr[2 * tid + 1] = __floats2half2_rn(r2, r3);
}

// ---------------- causal softmax (fp16 in/out, smem row cache) -------------
__global__ __launch_bounds__(256)
void softmax_h(const __half* __restrict__ sc, __half* __restrict__ a)
{
    const int m = blockIdx.x;
    const int b = blockIdx.y;
    const __half* row = sc + ((long)b * Sc + m) * (long)Sc;
    __half* orow = a + ((long)b * Sc + m) * (long)Sc;
    const int n = m + 1;
    const int tid = threadIdx.x;
    const int lane = tid & 31;
    const int wid = tid >> 5;

    __shared__ float sr[Sc];
    __shared__ float red[8];

    float lmax = -1e30f;
    for (int i = tid; i < n; i += 256) {
        const float v = __half2float(row[i]);
        sr[i] = v;
        lmax = fmaxf(lmax, v);
    }
#pragma unroll
    for (int o = 16; o > 0; o >>= 1)
        lmax = fmaxf(lmax, __shfl_xor_sync(0xffffffffu, lmax, o));
    if (lane == 0) red[wid] = lmax;
    __syncthreads();
    float gmax = -1e30f;
#pragma unroll
    for (int i = 0; i < 8; ++i) gmax = fmaxf(gmax, red[i]);
    __syncthreads();

    float lsum = 0.f;
    for (int i = tid; i < n; i += 256) {
        const float e = __expf(sr[i] - gmax);
        sr[i] = e;
        lsum += e;
    }
#pragma unroll
    for (int o = 16; o > 0; o >>= 1) lsum += __shfl_xor_sync(0xffffffffu, lsum, o);
    if (lane == 0) red[wid] = lsum;
    __syncthreads();
    float tot = 0.f;
#pragma unroll
    for (int i = 0; i < 8; ++i) tot += red[i];
    const float inv = 1.f / tot;

    for (int i = tid; i < n; i += 256)
        orow[i] = __float2half_rn(sr[i] * inv);
    const int lim = (m | 127);
    for (int i = n + tid; i <= lim; i += 256) orow[i] = __float2half_rn(0.f);
}

// ---- batched transpose f32 -> fp16 (6 weights) + fused bias concat --------
__global__ __launch_bounds__(256)
void trans_f2h6(const float* __restrict__ s0, const float* __restrict__ s1,
                const float* __restrict__ s2, const float* __restrict__ s3,
                const float* __restrict__ s4, const float* __restrict__ s5,
                __half* __restrict__ dstBase,
                const float* __restrict__ bq, const float* __restrict__ bk,
                const float* __restrict__ bv, float* __restrict__ bqkv)
{
    const int zi = blockIdx.z;
    const float* src = (zi == 0) ? s0 : (zi == 1) ? s1 : (zi == 2) ? s2
                    : (zi == 3) ? s3 : (zi == 4) ? s4 : s5;
    __half* dst = dstBase + (size_t)zi * Dc * Dc;

    __shared__ float t[32][33];
    const int c0 = blockIdx.x * 32;
    const int r0 = blockIdx.y * 32;
    const int tx = threadIdx.x, ty = threadIdx.y;  // 32 x 8
    const int ltid = ty * 32 + tx;

#pragma unroll
    for (int i = 0; i < 4; ++i)
        t[ty + 8 * i][tx] = src[(long)(r0 + ty + 8 * i) * Dc + c0 + tx];
    __syncthreads();

#pragma unroll
    for (int i = 0; i < 4; ++i) {
        const int c = c0 + ty + 8 * i;
        const int r = r0 + tx;
        dst[(long)c * Dc + r] = __float2half_rn(t[tx][ty + 8 * i]);
    }

    // bias concat piggybacked on one block
    if (zi == 0 && blockIdx.x == 0 && blockIdx.y == 0) {
#pragma unroll
        for (int i = 0; i < 4; ++i) {
            const int j = ltid + i * 256;
            bqkv[j] = bq[j];
            bqkv[Dc + j] = bk[j];
            bqkv[2 * Dc + j] = bv[j];
        }
    }
}

// ---------------- transpose fp16 -> fp16 (V slice of qkv), per batch -------
__global__ __launch_bounds__(256)
void trans_h2h(const __half* __restrict__ src, __half* __restrict__ dst,
               int R, int C, int srcStride, long srcBatch, long dstBatch)
{
    const int zb = blockIdx.z;
    src += (long)zb * srcBatch;
    dst += (long)zb * dstBatch;
    __shared__ __half t[32][34];
    const int c0 = blockIdx.x * 32;
    const int r0 = blockIdx.y * 32;
    const int tx = threadIdx.x, ty = threadIdx.y;

#pragma unroll
    for (int i = 0; i < 4; ++i)
        t[ty + 8 * i][tx] = src[(long)(r0 + ty + 8 * i) * srcStride + c0 + tx];
    __syncthreads();

#pragma unroll
    for (int i = 0; i < 4; ++i) {
        const int c = c0 + ty + 8 * i;
        const int r = r0 + tx;
        dst[(long)c * R + r] = t[tx][ty + 8 * i];
    }
}

// ---------------------------------------------------------------------------
extern "C" void kernel_launch(void* const* d_in, const int* in_sizes, int n_in,
                              void* d_out, int out_size)
{
    const float* x   = (const float*)d_in[0];
    const float* wq  = (const float*)d_in[1];
    const float* bq  = (const float*)d_in[2];
    const float* wk  = (const float*)d_in[3];
    const float* bk  = (const float*)d_in[4];
    const float* wv  = (const float*)d_in[5];
    const float* bv  = (const float*)d_in[6];
    const float* wo  = (const float*)d_in[7];
    const float* bo  = (const float*)d_in[8];
    const float* w1  = (const float*)d_in[9];
    const float* b1  = (const float*)d_in[10];
    const float* w2  = (const float*)d_in[11];
    const float* b2  = (const float*)d_in[12];
    const float* g1  = (const float*)d_in[13];
    const float* be1 = (const float*)d_in[14];
    const float* g2  = (const float*)d_in[15];
    const float* be2 = (const float*)d_in[16];
    float* out = (float*)d_out;

    __half *xn, *qkv, *vt, *s, *a, *ao, *m, *f, *wt;
    float *h, *bqkv;
    cudaGetSymbolAddress((void**)&xn,  g_xn);
    cudaGetSymbolAddress((void**)&qkv, g_qkv);
    cudaGetSymbolAddress((void**)&vt,  g_vt);
    cudaGetSymbolAddress((void**)&s,   g_s);
    cudaGetSymbolAddress((void**)&a,   g_a);
    cudaGetSymbolAddress((void**)&ao,  g_ao);
    cudaGetSymbolAddress((void**)&h,   g_h);
    cudaGetSymbolAddress((void**)&m,   g_m);
    cudaGetSymbolAddress((void**)&f,   g_f);
    cudaGetSymbolAddress((void**)&wt,  g_wt);
    cudaGetSymbolAddress((void**)&bqkv, g_bqkv);

    __half* wot = wt + 3L * Dc * Dc;
    __half* w1t = wt + 4L * Dc * Dc;
    __half* w2t = wt + 5L * Dc * Dc;

    cudaFuncSetAttribute((const void*)tgemm<E_HB,  false, false>, cudaFuncAttributeMaxDynamicSharedMemorySize, SMEM_SZ);
    cudaFuncSetAttribute((const void*)tgemm<E_H,   true,  false>, cudaFuncAttributeMaxDynamicSharedMemorySize, SMEM_SZ);
    cudaFuncSetAttribute((const void*)tgemm<E_H,   false, true >, cudaFuncAttributeMaxDynamicSharedMemorySize, SMEM_SZ);
    cudaFuncSetAttribute((const void*)tgemm<E_FBR, false, false>, cudaFuncAttributeMaxDynamicSharedMemorySize, SMEM_SZ);
    cudaFuncSetAttribute((const void*)tgemm<E_HBR, false, false>, cudaFuncAttributeMaxDynamicSharedMemorySize, SMEM_SZ);

    const float inv_sqrt_s = 1.0f / sqrtf((float)Sc);
    const dim3 tb(32, 8);
    const dim3 gW6(Dc / 32, Dc / 32, 6);
    const dim3 gV(Dc / 32, Sc / 32, Bc);
    const dim3 gQKV(D3 / 128, Mc / 128, 1);      // 24 x 64
    const dim3 gProj(Dc / 128, Mc / 128, 1);     // 8 x 64
    const dim3 gScore(Sc / 128, Sc / 128, Bc);   // 16 x 16 x 4
    const dim3 gAV(Dc / 128, Sc / 128, Bc);      // 8 x 16 x 4

    // weight transposes + bias concat (one launch)
    trans_f2h6<<<gW6, tb>>>(wq, wk, wv, wo, w1, w2, wt, bq, bk, bv, bqkv);

    // LN1 -> xn (fp16)
    layernorm_h<<<Mc, 256>>>(x, g1, be1, xn);

    // fused QKV projection: [M,1024] @ [3072,1024]^T -> [M,3072] fp16
    tgemm<E_HB, false, false><<<gQKV, 128, SMEM_SZ>>>(
        xn, wt, bqkv, nullptr, qkv, Dc, D3, 1.f, 0, 0, 0, Dc, Dc);

    // v slice -> vt (transpose per batch)
    trans_h2h<<<gV, tb>>>(qkv + 2 * Dc, vt, Sc, Dc, D3,
                          (long)Sc * D3, (long)Dc * Sc);

    // scores = (q k^T)/sqrt(S), causal tiles skipped (fp16 out)
    tgemm<E_H, true, false><<<gScore, 128, SMEM_SZ>>>(
        qkv, qkv + Dc, nullptr, nullptr, s, Dc, Sc, inv_sqrt_s,
        Sc, Sc, Sc, D3, D3);

    // softmax -> a (fp16 + zero pad)
    softmax_h<<<dim3(Sc, Bc), 256>>>(s, a);

    // attn @ V with block-K limit -> ao (fp16)
    tgemm<E_H, false, true><<<gAV, 128, SMEM_SZ>>>(
        a, vt, nullptr, nullptr, ao, Sc, Dc, 1.f, Sc, Dc, Sc, Sc, Sc);

    // h = ao @ wo + bo + x (f32)
    tgemm<E_FBR, false, false><<<gProj, 128, SMEM_SZ>>>(
        ao, wot, bo, x, h, Dc, Dc, 1.f, 0, 0, 0, Dc, Dc);

    // LN2 -> m (fp16)
    layernorm_h<<<Mc, 256>>>(h, g2, be2, m);

    // f = relu(m @ w1 + b1) (fp16)
    tgemm<E_HBR, false, false><<<gProj, 128, SMEM_SZ>>>(
        m, w1t, b1, nullptr, f, Dc, Dc, 1.f, 0, 0, 0, Dc, Dc);

    // out = f @ w2 + b2 + h (f32)
    tgemm<E_FBR, false, false><<<gProj, 128, SMEM_SZ>>>(
        f, w2t, b2, h, out, Dc, Dc, 1.f, 0, 0, 0, Dc, Dc);
}

// round 16
// speedup vs baseline: 1.6238x; 1.0133x over previous
#include <cuda_runtime.h>
#include <cuda_fp16.h>
#include <math.h>
#include <stdint.h>

// ---------------- problem shape ----------------
#define Bc 4
#define Sc 2048
#define Dc 1024
#define Mc (Bc * Sc)
#define D3 (3 * Dc)

// ---------------- scratch (device globals; no allocation allowed) ----------
__device__ __align__(256) __half g_xn  [(size_t)Mc * Dc];
__device__ __align__(256) __half g_qkv [(size_t)Mc * D3];
__device__ __align__(256) __half g_vt  [(size_t)Bc * Dc * Sc];
__device__ __align__(256) __half g_s   [(size_t)Bc * Sc * Sc];
__device__ __align__(256) __half g_a   [(size_t)Bc * Sc * Sc];
__device__ __align__(256) __half g_ao  [(size_t)Mc * Dc];
__device__ __align__(256) float  g_h   [(size_t)Mc * Dc];
__device__ __align__(256) __half g_m   [(size_t)Mc * Dc];
__device__ __align__(256) __half g_f   [(size_t)Mc * Dc];
__device__ __align__(256) __half g_wt  [6][(size_t)Dc * Dc];
__device__ __align__(256) float  g_bqkv[D3];

// ---------------- PTX helpers ----------------
__device__ __forceinline__ uint32_t s2u(const void* p) {
    uint32_t a;
    asm("{ .reg .u64 t; cvta.to.shared.u64 t, %1; cvt.u32.u64 %0, t; }"
        : "=r"(a) : "l"(p));
    return a;
}
__device__ __forceinline__ void cp16(uint32_t s, const void* g) {
    asm volatile("cp.async.cg.shared.global [%0], [%1], 16;" :: "r"(s), "l"(g));
}
#define CP_COMMIT() asm volatile("cp.async.commit_group;" ::: "memory")
#define CP_WAIT1()  asm volatile("cp.async.wait_group 1;" ::: "memory")

__device__ __forceinline__ void ldmat4(uint32_t (&r)[4], uint32_t addr) {
    asm volatile("ldmatrix.sync.aligned.m8n8.x4.shared.b16 {%0,%1,%2,%3}, [%4];"
                 : "=r"(r[0]), "=r"(r[1]), "=r"(r[2]), "=r"(r[3]) : "r"(addr));
}
__device__ __forceinline__ void mma16816(float (&d)[4], const uint32_t (&a)[4],
                                         const uint32_t b0, const uint32_t b1) {
    asm volatile(
        "mma.sync.aligned.m16n8k16.row.col.f32.f16.f16.f32 "
        "{%0,%1,%2,%3},{%4,%5,%6,%7},{%8,%9},{%0,%1,%2,%3};"
        : "+f"(d[0]), "+f"(d[1]), "+f"(d[2]), "+f"(d[3])
        : "r"(a[0]), "r"(a[1]), "r"(a[2]), "r"(a[3]), "r"(b0), "r"(b1));
}

// ---------------- fp16 mma GEMM (64x64 warp tile, 3-stage, BK=64) ----------
// C = alpha * A[.,K] (x) B[.,K]^T    (both operands row-major over K, strided)
#define E_FBR  2
#define E_H    7
#define E_HB   8
#define E_HBR  9
#define E_QKVT 10   // like E_HB, plus transposed V store for cols >= 2*Dc

#define BKA 64                         // K per stage (fp16)
#define SSTR 72                        // padded smem row stride in halves (144 B)
#define STG_B (128 * SSTR * 2)         // one operand tile = 18432 B
#define STAGE_B (2 * STG_B)            // A+B per stage   = 36864 B
#define NSTG 3
#define SMEM_SZ (NSTG * STAGE_B)       // 110592 B

template <int EPI, bool CSKIP, bool CKLIM>
__global__ __launch_bounds__(128, 2)
void tgemm(const __half* __restrict__ A2, const __half* __restrict__ B2,
           const float* __restrict__ bias, const float* __restrict__ res,
           void* __restrict__ Cp, int Ksrc, int Nsrc, float alpha,
           long aRows, long bRows, long cRows, int lda, int ldb)
{
    const int brow = blockIdx.y * 128;
    const int bcol = blockIdx.x * 128;
    if (CSKIP && bcol > brow + 127) return;
    const int z = blockIdx.z;

    extern __shared__ __align__(16) char smem[];
    const uint32_t sb = s2u(smem);

    const int tid = threadIdx.x;
    const int lane = tid & 31;
    const int w = tid >> 5;
    const int wm = (w & 1) * 64;
    const int wn = (w >> 1) * 64;

    const __half* Arow = A2 + ((long)z * aRows + brow) * (long)lda;
    const __half* Brow = B2 + ((long)z * bRows + bcol) * (long)ldb;

    const int nk = (CKLIM ? min(Ksrc, brow + 128) : Ksrc) / BKA;

    float acc[4][8][4];
#pragma unroll
    for (int i = 0; i < 4; ++i)
#pragma unroll
        for (int j = 0; j < 8; ++j)
#pragma unroll
            for (int u = 0; u < 4; ++u) acc[i][j][u] = 0.f;

    auto load_tile = [&](int t) {
        const int k0 = t * BKA;
        const uint32_t base = sb + (t % NSTG) * STAGE_B;
#pragma unroll
        for (int it = 0; it < 8; ++it) {
            const int idx = tid + it * 128;
            const int row = idx >> 3;
            const int ch  = idx & 7;
            const uint32_t off = row * (SSTR * 2) + ch * 16;
            cp16(base + off,         Arow + (long)row * lda + k0 + ch * 8);
            cp16(base + STG_B + off, Brow + (long)row * ldb + k0 + ch * 8);
        }
    };

    const int a_moff = lane & 15;
    const int a_koff = (lane >> 4) * 8;
    const int b_noff = (lane & 7) + (lane >> 4) * 8;
    const int b_koff = ((lane >> 3) & 1) * 8;

    load_tile(0); CP_COMMIT();
    load_tile(1); CP_COMMIT();
    CP_WAIT1();
    __syncthreads();

    for (int t = 0; t < nk; ++t) {
        if (t + 2 < nk) load_tile(t + 2);
        CP_COMMIT();

        const uint32_t abase = sb + (t % NSTG) * STAGE_B;
        const uint32_t bbase = abase + STG_B;
#pragma unroll
        for (int ks = 0; ks < 4; ++ks) {
            uint32_t a[4][4];
#pragma unroll
            for (int mi = 0; mi < 4; ++mi)
                ldmat4(a[mi], abase + (uint32_t)((wm + mi * 16 + a_moff) * (SSTR * 2)
                                                 + (ks * 16 + a_koff) * 2));
            uint32_t b[8][2];
#pragma unroll
            for (int np = 0; np < 4; ++np) {
                uint32_t bb[4];
                ldmat4(bb, bbase + (uint32_t)((wn + np * 16 + b_noff) * (SSTR * 2)
                                              + (ks * 16 + b_koff) * 2));
                b[np * 2][0] = bb[0]; b[np * 2][1] = bb[1];
                b[np * 2 + 1][0] = bb[2]; b[np * 2 + 1][1] = bb[3];
            }
#pragma unroll
            for (int mi = 0; mi < 4; ++mi)
#pragma unroll
                for (int nj = 0; nj < 8; ++nj)
                    mma16816(acc[mi][nj], a[mi], b[nj][0], b[nj][1]);
        }
        CP_WAIT1();
        __syncthreads();
    }

    // ---------------- epilogue ----------------
#pragma unroll
    for (int mi = 0; mi < 4; ++mi) {
#pragma unroll
        for (int half_ = 0; half_ < 2; ++half_) {
            const int r = brow + wm + mi * 16 + (lane >> 2) + half_ * 8;
#pragma unroll
            for (int nj = 0; nj < 8; ++nj) {
                const int c = bcol + wn + nj * 8 + 2 * (lane & 3);
                float v0 = acc[mi][nj][half_ * 2 + 0] * alpha;
                float v1 = acc[mi][nj][half_ * 2 + 1] * alpha;

                if (EPI == E_FBR) {
                    v0 += bias[c]; v1 += bias[c + 1];
                    const float2 rv = *reinterpret_cast<const float2*>(
                        res + (long)r * Nsrc + c);
                    v0 += rv.x; v1 += rv.y;
                    float2 o; o.x = v0; o.y = v1;
                    *reinterpret_cast<float2*>(
                        (float*)Cp + ((long)z * cRows + r) * (long)Nsrc + c) = o;
                } else {
                    if (EPI == E_HB || EPI == E_HBR || EPI == E_QKVT) {
                        v0 += bias[c]; v1 += bias[c + 1];
                    }
                    if (EPI == E_HBR) { v0 = fmaxf(v0, 0.f); v1 = fmaxf(v1, 0.f); }
                    __half2 o2 = __floats2half2_rn(v0, v1);
                    *reinterpret_cast<__half2*>(
                        (__half*)Cp + ((long)z * cRows + r) * (long)Nsrc + c) = o2;
                    if (EPI == E_QKVT && c >= 2 * Dc) {
                        // transposed V store: vt[b][d][s]
                        __half* vtp = (__half*)res;
                        const int bb2 = r >> 11;        // r / 2048
                        const int sidx = r & 2047;
                        const int d = c - 2 * Dc;
                        vtp[((long)bb2 * Dc + d) * Sc + sidx]       = __low2half(o2);
                        vtp[((long)bb2 * Dc + d + 1) * Sc + sidx]   = __high2half(o2);
                    }
                }
            }
        }
    }
}

// ---------------- LayerNorm -> fp16 output (vectorized) ----------------
__global__ __launch_bounds__(256)
void layernorm_h(const float* __restrict__ x, const float* __restrict__ gamma,
                 const float* __restrict__ beta, __half* __restrict__ y)
{
    const long rowi = blockIdx.x;
    const int tid = threadIdx.x;
    const int lane = tid & 31;
    const int wid = tid >> 5;
    __shared__ float ws[8];

    const float4 xv = reinterpret_cast<const float4*>(x + rowi * Dc)[tid];

    float s = xv.x + xv.y + xv.z + xv.w;
#pragma unroll
    for (int o = 16; o > 0; o >>= 1) s += __shfl_xor_sync(0xffffffffu, s, o);
    if (lane == 0) ws[wid] = s;
    __syncthreads();
    float tot = 0.f;
#pragma unroll
    for (int i = 0; i < 8; ++i) tot += ws[i];
    const float mean = tot * (1.f / (float)Dc);
    __syncthreads();

    const float d0 = xv.x - mean, d1 = xv.y - mean, d2 = xv.z - mean, d3 = xv.w - mean;
    float v = d0 * d0 + d1 * d1 + d2 * d2 + d3 * d3;
#pragma unroll
    for (int o = 16; o > 0; o >>= 1) v += __shfl_xor_sync(0xffffffffu, v, o);
    if (lane == 0) ws[wid] = v;
    __syncthreads();
    float vtot = 0.f;
#pragma unroll
    for (int i = 0; i < 8; ++i) vtot += ws[i];
    const float var = vtot * (1.f / (float)(Dc - 1));   // ddof=1
    const float inv = 1.f / (sqrtf(var) + 1e-6f);       // eps on std

    const float4 gv = reinterpret_cast<const float4*>(gamma)[tid];
    const float4 bv = reinterpret_cast<const float4*>(beta)[tid];
    const float r0 = gv.x * d0 * inv + bv.x;
    const float r1 = gv.y * d1 * inv + bv.y;
    const float r2 = gv.z * d2 * inv + bv.z;
    const float r3 = gv.w * d3 * inv + bv.w;

    __half2* yr = reinterpret_cast<__half2*>(y + rowi * Dc);
    yr[2 * tid]     = __floats2half2_rn(r0, r1);
    yr[2 * tid + 1] = __floats2half2_rn(r2, r3);
}

// -------- causal softmax (fp16 in/out, vectorized, smem row cache) ---------
// Over-reading one in-tile element past the diagonal only raises the max
// shift (softmax is shift-invariant); the sum/output loops use the exact bound.
__global__ __launch_bounds__(256)
void softmax_h(const __half* __restrict__ sc, __half* __restrict__ a)
{
    const int m = blockIdx.x;
    const int b = blockIdx.y;
    const __half2* row2 = reinterpret_cast<const __half2*>(
        sc + ((long)b * Sc + m) * (long)Sc);
    __half2* orow2 = reinterpret_cast<__half2*>(
        a + ((long)b * Sc + m) * (long)Sc);
    const int n = m + 1;
    const int n2 = (n + 1) >> 1;      // half2 pairs covering [0, n)
    const int tid = threadIdx.x;
    const int lane = tid & 31;
    const int wid = tid >> 5;

    __shared__ float sr[Sc];
    __shared__ float red[8];

    float lmax = -1e30f;
    for (int i = tid; i < n2; i += 256) {
        const float2 v = __half22float2(row2[i]);
        sr[2 * i]     = v.x;
        sr[2 * i + 1] = v.y;
        lmax = fmaxf(lmax, fmaxf(v.x, v.y));
    }
#pragma unroll
    for (int o = 16; o > 0; o >>= 1)
        lmax = fmaxf(lmax, __shfl_xor_sync(0xffffffffu, lmax, o));
    if (lane == 0) red[wid] = lmax;
    __syncthreads();
    float gmax = -1e30f;
#pragma unroll
    for (int i = 0; i < 8; ++i) gmax = fmaxf(gmax, red[i]);
    __syncthreads();

    float lsum = 0.f;
    for (int i = tid; i < n; i += 256) {
        const float e = __expf(sr[i] - gmax);
        sr[i] = e;
        lsum += e;
    }
#pragma unroll
    for (int o = 16; o > 0; o >>= 1) lsum += __shfl_xor_sync(0xffffffffu, lsum, o);
    if (lane == 0) red[wid] = lsum;
    __syncthreads();
    float tot = 0.f;
#pragma unroll
    for (int i = 0; i < 8; ++i) tot += red[i];
    const float inv = 1.f / tot;

    // write probs + zero pad through (m|127), as half2 pairs (exact: lim+1 % 128 == 0)
    const int lim2 = ((m | 127) + 1) >> 1;
    for (int i = tid; i < lim2; i += 256) {
        const int i0 = 2 * i, i1 = 2 * i + 1;
        const float v0 = (i0 < n) ? sr[i0] * inv : 0.f;
        const float v1 = (i1 < n) ? sr[i1] * inv : 0.f;
        orow2[i] = __floats2half2_rn(v0, v1);
    }
}

// ---- batched transpose f32 -> fp16 (6 weights) + fused bias concat --------
__global__ __launch_bounds__(256)
void trans_f2h6(const float* __restrict__ s0, const float* __restrict__ s1,
                const float* __restrict__ s2, const float* __restrict__ s3,
                const float* __restrict__ s4, const float* __restrict__ s5,
                __half* __restrict__ dstBase,
                const float* __restrict__ bq, const float* __restrict__ bk,
                const float* __restrict__ bv, float* __restrict__ bqkv)
{
    const int zi = blockIdx.z;
    const float* src = (zi == 0) ? s0 : (zi == 1) ? s1 : (zi == 2) ? s2
                    : (zi == 3) ? s3 : (zi == 4) ? s4 : s5;
    __half* dst = dstBase + (size_t)zi * Dc * Dc;

    __shared__ float t[32][33];
    const int c0 = blockIdx.x * 32;
    const int r0 = blockIdx.y * 32;
    const int tx = threadIdx.x, ty = threadIdx.y;  // 32 x 8
    const int ltid = ty * 32 + tx;

#pragma unroll
    for (int i = 0; i < 4; ++i)
        t[ty + 8 * i][tx] = src[(long)(r0 + ty + 8 * i) * Dc + c0 + tx];
    __syncthreads();

#pragma unroll
    for (int i = 0; i < 4; ++i) {
        const int c = c0 + ty + 8 * i;
        const int r = r0 + tx;
        dst[(long)c * Dc + r] = __float2half_rn(t[tx][ty + 8 * i]);
    }

    // bias concat piggybacked on one block
    if (zi == 0 && blockIdx.x == 0 && blockIdx.y == 0) {
#pragma unroll
        for (int i = 0; i < 4; ++i) {
            const int j = ltid + i * 256;
            bqkv[j] = bq[j];
            bqkv[Dc + j] = bk[j];
            bqkv[2 * Dc + j] = bv[j];
        }
    }
}

// ---------------------------------------------------------------------------
extern "C" void kernel_launch(void* const* d_in, const int* in_sizes, int n_in,
                              void* d_out, int out_size)
{
    const float* x   = (const float*)d_in[0];
    const float* wq  = (const float*)d_in[1];
    const float* bq  = (const float*)d_in[2];
    const float* wk  = (const float*)d_in[3];
    const float* bk  = (const float*)d_in[4];
    const float* wv  = (const float*)d_in[5];
    const float* bv  = (const float*)d_in[6];
    const float* wo  = (const float*)d_in[7];
    const float* bo  = (const float*)d_in[8];
    const float* w1  = (const float*)d_in[9];
    const float* b1  = (const float*)d_in[10];
    const float* w2  = (const float*)d_in[11];
    const float* b2  = (const float*)d_in[12];
    const float* g1  = (const float*)d_in[13];
    const float* be1 = (const float*)d_in[14];
    const float* g2  = (const float*)d_in[15];
    const float* be2 = (const float*)d_in[16];
    float* out = (float*)d_out;

    __half *xn, *qkv, *vt, *s, *a, *ao, *m, *f, *wt;
    float *h, *bqkv;
    cudaGetSymbolAddress((void**)&xn,  g_xn);
    cudaGetSymbolAddress((void**)&qkv, g_qkv);
    cudaGetSymbolAddress((void**)&vt,  g_vt);
    cudaGetSymbolAddress((void**)&s,   g_s);
    cudaGetSymbolAddress((void**)&a,   g_a);
    cudaGetSymbolAddress((void**)&ao,  g_ao);
    cudaGetSymbolAddress((void**)&h,   g_h);
    cudaGetSymbolAddress((void**)&m,   g_m);
    cudaGetSymbolAddress((void**)&f,   g_f);
    cudaGetSymbolAddress((void**)&wt,  g_wt);
    cudaGetSymbolAddress((void**)&bqkv, g_bqkv);

    __half* wot = wt + 3L * Dc * Dc;
    __half* w1t = wt + 4L * Dc * Dc;
    __half* w2t = wt + 5L * Dc * Dc;

    cudaFuncSetAttribute((const void*)tgemm<E_QKVT, false, false>, cudaFuncAttributeMaxDynamicSharedMemorySize, SMEM_SZ);
    cudaFuncSetAttribute((const void*)tgemm<E_H,    true,  false>, cudaFuncAttributeMaxDynamicSharedMemorySize, SMEM_SZ);
    cudaFuncSetAttribute((const void*)tgemm<E_H,    false, true >, cudaFuncAttributeMaxDynamicSharedMemorySize, SMEM_SZ);
    cudaFuncSetAttribute((const void*)tgemm<E_FBR,  false, false>, cudaFuncAttributeMaxDynamicSharedMemorySize, SMEM_SZ);
    cudaFuncSetAttribute((const void*)tgemm<E_HBR,  false, false>, cudaFuncAttributeMaxDynamicSharedMemorySize, SMEM_SZ);

    const float inv_sqrt_s = 1.0f / sqrtf((float)Sc);
    const dim3 tb(32, 8);
    const dim3 gW6(Dc / 32, Dc / 32, 6);
    const dim3 gQKV(D3 / 128, Mc / 128, 1);      // 24 x 64
    const dim3 gProj(Dc / 128, Mc / 128, 1);     // 8 x 64
    const dim3 gScore(Sc / 128, Sc / 128, Bc);   // 16 x 16 x 4
    const dim3 gAV(Dc / 128, Sc / 128, Bc);      // 8 x 16 x 4

    // weight transposes + bias concat (one launch)
    trans_f2h6<<<gW6, tb>>>(wq, wk, wv, wo, w1, w2, wt, bq, bk, bv, bqkv);

    // LN1 -> xn (fp16)
    layernorm_h<<<Mc, 256>>>(x, g1, be1, xn);

    // fused QKV projection with in-epilogue V transpose:
    // [M,1024] @ [3072,1024]^T -> qkv [M,3072] fp16 (+ vt [B,D,S])
    tgemm<E_QKVT, false, false><<<gQKV, 128, SMEM_SZ>>>(
        xn, wt, bqkv, (const float*)vt, qkv, Dc, D3, 1.f, 0, 0, 0, Dc, Dc);

    // scores = (q k^T)/sqrt(S), causal tiles skipped (fp16 out)
    tgemm<E_H, true, false><<<gScore, 128, SMEM_SZ>>>(
        qkv, qkv + Dc, nullptr, nullptr, s, Dc, Sc, inv_sqrt_s,
        Sc, Sc, Sc, D3, D3);

    // softmax -> a (fp16 + zero pad)
    softmax_h<<<dim3(Sc, Bc), 256>>>(s, a);

    // attn @ V with block-K limit -> ao (fp16)
    tgemm<E_H, false, true><<<gAV, 128, SMEM_SZ>>>(
        a, vt, nullptr, nullptr, ao, Sc, Dc, 1.f, Sc, Dc, Sc, Sc, Sc);

    // h = ao @ wo + bo + x (f32)
    tgemm<E_FBR, false, false><<<gProj, 128, SMEM_SZ>>>(
        ao, wot, bo, x, h, Dc, Dc, 1.f, 0, 0, 0, Dc, Dc);

    // LN2 -> m (fp16)
    layernorm_h<<<Mc, 256>>>(h, g2, be2, m);

    // f = relu(m @ w1 + b1) (fp16)
    tgemm<E_HBR, false, false><<<gProj, 128, SMEM_SZ>>>(
        m, w1t, b1, nullptr, f, Dc, Dc, 1.f, 0, 0, 0, Dc, Dc);

    // out = f @ w2 + b2 + h (f32)
    tgemm<E_FBR, false, false><<<gProj, 128, SMEM_SZ>>>(
        f, w2t, b2, h, out, Dc, Dc, 1.f, 0, 0, 0, Dc, Dc);
}